// round 1
// baseline (speedup 1.0000x reference)
#include <cuda_runtime.h>
#include <math.h>

#define DMODEL 1024
#define SEQT   2048
#define BATCH  2
#define MROWS  4096   // BATCH * SEQT
#define NHEAD  16
#define HDIM   64

// ---------------- scratch (static device allocations) ----------------
__device__ float g_ln [MROWS * DMODEL];
__device__ float g_q  [MROWS * DMODEL];
__device__ float g_k  [MROWS * DMODEL];
__device__ float g_v  [MROWS * DMODEL];
__device__ float g_ctx[MROWS * DMODEL];
__device__ float g_x2 [MROWS * DMODEL];
__device__ float g_ff [MROWS * 2 * DMODEL];

// ---------------- f32x2 packed helpers (sm_103a full-rate fp32) ------
__device__ __forceinline__ unsigned long long pack2(float x, float y) {
    unsigned long long r;
    asm("mov.b64 %0, {%1, %2};" : "=l"(r) : "f"(x), "f"(y));
    return r;
}
__device__ __forceinline__ void unpack2(unsigned long long v, float& x, float& y) {
    asm("mov.b64 {%0, %1}, %2;" : "=f"(x), "=f"(y) : "l"(v));
}
__device__ __forceinline__ unsigned long long fma2(unsigned long long a,
                                                   unsigned long long b,
                                                   unsigned long long c) {
    unsigned long long d;
    asm("fma.rn.f32x2 %0, %1, %2, %3;" : "=l"(d) : "l"(a), "l"(b), "l"(c));
    return d;
}

__device__ __forceinline__ float gelu_exact(float x) {
    return 0.5f * x * (1.0f + erff(x * 0.70710678118654752f));
}

// ---------------- LayerNorm: one block per row, 256 threads ----------
__global__ void __launch_bounds__(256) ln_kernel(const float* __restrict__ x,
                                                 const float* __restrict__ g,
                                                 const float* __restrict__ b,
                                                 float* __restrict__ out) {
    int row = blockIdx.x;
    int tid = threadIdx.x;
    const float4* xr = (const float4*)(x + (size_t)row * DMODEL);
    float4 v = xr[tid];
    float s  = v.x + v.y + v.z + v.w;
    float ss = v.x * v.x + v.y * v.y + v.z * v.z + v.w * v.w;
    #pragma unroll
    for (int o = 16; o > 0; o >>= 1) {
        s  += __shfl_xor_sync(0xffffffffu, s,  o);
        ss += __shfl_xor_sync(0xffffffffu, ss, o);
    }
    __shared__ float sh[16];
    int w = tid >> 5;
    if ((tid & 31) == 0) { sh[w] = s; sh[8 + w] = ss; }
    __syncthreads();
    if (tid < 32) {
        float a  = (tid < 8) ? sh[tid]     : 0.0f;
        float a2 = (tid < 8) ? sh[8 + tid] : 0.0f;
        #pragma unroll
        for (int o = 4; o > 0; o >>= 1) {
            a  += __shfl_xor_sync(0xffffffffu, a,  o);
            a2 += __shfl_xor_sync(0xffffffffu, a2, o);
        }
        if (tid == 0) { sh[0] = a; sh[1] = a2; }
    }
    __syncthreads();
    float mean = sh[0] * (1.0f / DMODEL);
    float var  = sh[1] * (1.0f / DMODEL) - mean * mean;
    float rstd = rsqrtf(var + 1e-5f);
    float4 gg = ((const float4*)g)[tid];
    float4 bb = ((const float4*)b)[tid];
    float4 o4;
    o4.x = (v.x - mean) * rstd * gg.x + bb.x;
    o4.y = (v.y - mean) * rstd * gg.y + bb.y;
    o4.z = (v.z - mean) * rstd * gg.z + bb.z;
    o4.w = (v.w - mean) * rstd * gg.w + bb.w;
    ((float4*)(out + (size_t)row * DMODEL))[tid] = o4;
}

// ---------------- SGEMM 128x128x8, 256 thr, 8x8 microtile, f32x2 -----
// C[M,N] = A[M,K] @ B[K,N]  (+bias) (+gelu) (+res)
template <int GELU, int HAS_BIAS, int HAS_RES>
__global__ void __launch_bounds__(256) sgemm_kernel(
    const float* __restrict__ A, const float* __restrict__ B,
    const float* __restrict__ bias, const float* __restrict__ res,
    float* __restrict__ C, int M, int N, int K) {
    __shared__ float As[8][132];   // A^T tile, padded
    __shared__ float Bs[8][128];

    int tid = threadIdx.x;
    int bm = blockIdx.y * 128;
    int bn = blockIdx.x * 128;
    int tx = tid & 15;
    int ty = tid >> 4;

    unsigned long long acc[8][4];
    #pragma unroll
    for (int i = 0; i < 8; ++i)
        #pragma unroll
        for (int j = 0; j < 4; ++j) acc[i][j] = 0ull;

    int arow = tid >> 1, acol = (tid & 1) * 4;
    int brow = tid >> 5, bcol = (tid & 31) * 4;
    const float* Aptr = A + (size_t)(bm + arow) * K + acol;
    const float* Bptr = B + (size_t)brow * N + bn + bcol;

    for (int kt = 0; kt < K; kt += 8) {
        float4 av = *(const float4*)(Aptr + kt);
        float4 bv = *(const float4*)(Bptr + (size_t)kt * N);
        As[acol + 0][arow] = av.x;
        As[acol + 1][arow] = av.y;
        As[acol + 2][arow] = av.z;
        As[acol + 3][arow] = av.w;
        *(float4*)&Bs[brow][bcol] = bv;
        __syncthreads();
        #pragma unroll
        for (int k = 0; k < 8; ++k) {
            float4 a0 = *(const float4*)&As[k][ty * 8];
            float4 a1 = *(const float4*)&As[k][ty * 8 + 4];
            const unsigned long long* bp =
                (const unsigned long long*)&Bs[k][tx * 8];
            unsigned long long b0 = bp[0], b1 = bp[1], b2 = bp[2], b3 = bp[3];
            unsigned long long a2[8];
            a2[0] = pack2(a0.x, a0.x); a2[1] = pack2(a0.y, a0.y);
            a2[2] = pack2(a0.z, a0.z); a2[3] = pack2(a0.w, a0.w);
            a2[4] = pack2(a1.x, a1.x); a2[5] = pack2(a1.y, a1.y);
            a2[6] = pack2(a1.z, a1.z); a2[7] = pack2(a1.w, a1.w);
            #pragma unroll
            for (int i = 0; i < 8; ++i) {
                acc[i][0] = fma2(a2[i], b0, acc[i][0]);
                acc[i][1] = fma2(a2[i], b1, acc[i][1]);
                acc[i][2] = fma2(a2[i], b2, acc[i][2]);
                acc[i][3] = fma2(a2[i], b3, acc[i][3]);
            }
        }
        __syncthreads();
    }

    #pragma unroll
    for (int i = 0; i < 8; ++i) {
        int row = bm + ty * 8 + i;
        #pragma unroll
        for (int jp = 0; jp < 4; ++jp) {
            float c0, c1;
            unpack2(acc[i][jp], c0, c1);
            int col = bn + tx * 8 + jp * 2;
            if (HAS_BIAS) { c0 += bias[col]; c1 += bias[col + 1]; }
            if (GELU) { c0 = gelu_exact(c0); c1 = gelu_exact(c1); }
            if (HAS_RES) {
                const float* r = res + (size_t)row * N + col;
                c0 += r[0]; c1 += r[1];
            }
            float2 o; o.x = c0; o.y = c1;
            *(float2*)(C + (size_t)row * N + col) = o;
        }
    }
}

// ---------------- Flash attention: 64q x 64k tiles, fp32 -------------
// grid (32 qtiles, 32 b*h), 256 threads, thread = (tx 0..15 over k/d, ty 0..15 over q)
__global__ void __launch_bounds__(256) attn_kernel(
    const float* __restrict__ Q, const float* __restrict__ K,
    const float* __restrict__ V, float* __restrict__ O) {
    __shared__ float Qs [64 * 64];  // [q][d], pre-scaled
    __shared__ float KVs[64 * 64];  // K phase: [d][k^sw]; V phase: [k][d]
    __shared__ float Ps [64 * 64];  // [q][k]

    int qt = 31 - (int)blockIdx.x;        // heavy tiles first
    int bh = blockIdx.y;
    int b = bh >> 4, h = bh & 15;
    int tid = threadIdx.x;
    int tx = tid & 15, ty = tid >> 4;

    size_t base = ((size_t)b * SEQT) * DMODEL + (size_t)h * HDIM;

    // load Q tile (scaled by 1/sqrt(HD))
    #pragma unroll
    for (int r = 0; r < 16; ++r) {
        int idx = r * 256 + tid;
        int qr = idx >> 6, d = idx & 63;
        Qs[qr * 64 + d] = Q[base + (size_t)(qt * 64 + qr) * DMODEL + d] * 0.125f;
    }

    float m[4], l[4], acc[4][4];
    #pragma unroll
    for (int i = 0; i < 4; ++i) {
        m[i] = -1e30f; l[i] = 0.0f;
        #pragma unroll
        for (int j = 0; j < 4; ++j) acc[i][j] = 0.0f;
    }

    for (int kt = 0; kt <= qt; ++kt) {
        __syncthreads();  // protect KVs (V of previous iter) and Q first pass
        // K tile, transposed [d][k], XOR-swizzled so writes are conflict-free
        #pragma unroll
        for (int r = 0; r < 16; ++r) {
            int idx = r * 256 + tid;
            int kr = idx >> 6, d = idx & 63;
            KVs[d * 64 + (kr ^ (d & 31))] =
                K[base + (size_t)(kt * 64 + kr) * DMODEL + d];
        }
        __syncthreads();

        float s[4][4];
        #pragma unroll
        for (int i = 0; i < 4; ++i)
            #pragma unroll
            for (int j = 0; j < 4; ++j) s[i][j] = 0.0f;

        #pragma unroll 4
        for (int d = 0; d < 64; ++d) {
            int c = d & 31;
            float a0 = Qs[(ty * 4 + 0) * 64 + d];
            float a1 = Qs[(ty * 4 + 1) * 64 + d];
            float a2 = Qs[(ty * 4 + 2) * 64 + d];
            float a3 = Qs[(ty * 4 + 3) * 64 + d];
            const float* kd = &KVs[d * 64];
            float b0 = kd[(tx * 4 + 0) ^ c];
            float b1 = kd[(tx * 4 + 1) ^ c];
            float b2 = kd[(tx * 4 + 2) ^ c];
            float b3 = kd[(tx * 4 + 3) ^ c];
            s[0][0] += a0 * b0; s[0][1] += a0 * b1; s[0][2] += a0 * b2; s[0][3] += a0 * b3;
            s[1][0] += a1 * b0; s[1][1] += a1 * b1; s[1][2] += a1 * b2; s[1][3] += a1 * b3;
            s[2][0] += a2 * b0; s[2][1] += a2 * b1; s[2][2] += a2 * b2; s[2][3] += a2 * b3;
            s[3][0] += a3 * b0; s[3][1] += a3 * b1; s[3][2] += a3 * b2; s[3][3] += a3 * b3;
        }

        if (kt == qt) {  // causal mask on diagonal tile
            #pragma unroll
            for (int i = 0; i < 4; ++i)
                #pragma unroll
                for (int j = 0; j < 4; ++j)
                    if (tx * 4 + j > ty * 4 + i) s[i][j] = -1e30f;
        }

        // online softmax (row groups = 16 lanes sharing ty)
        #pragma unroll
        for (int i = 0; i < 4; ++i) {
            float t = fmaxf(fmaxf(s[i][0], s[i][1]), fmaxf(s[i][2], s[i][3]));
            #pragma unroll
            for (int o = 1; o < 16; o <<= 1)
                t = fmaxf(t, __shfl_xor_sync(0xffffffffu, t, o));
            float mn = fmaxf(m[i], t);
            float p0 = __expf(s[i][0] - mn);
            float p1 = __expf(s[i][1] - mn);
            float p2 = __expf(s[i][2] - mn);
            float p3 = __expf(s[i][3] - mn);
            float* pr = &Ps[(ty * 4 + i) * 64 + tx * 4];
            pr[0] = p0; pr[1] = p1; pr[2] = p2; pr[3] = p3;
            float su = p0 + p1 + p2 + p3;
            #pragma unroll
            for (int o = 1; o < 16; o <<= 1)
                su += __shfl_xor_sync(0xffffffffu, su, o);
            float alpha = __expf(m[i] - mn);
            l[i] = l[i] * alpha + su;
            acc[i][0] *= alpha; acc[i][1] *= alpha;
            acc[i][2] *= alpha; acc[i][3] *= alpha;
            m[i] = mn;
        }
        __syncthreads();  // Ps written, K reads done -> safe to overwrite KVs

        // V tile, row-major [k][d]
        #pragma unroll
        for (int r = 0; r < 16; ++r) {
            int idx = r * 256 + tid;
            int kr = idx >> 6, d = idx & 63;
            KVs[kr * 64 + d] = V[base + (size_t)(kt * 64 + kr) * DMODEL + d];
        }
        __syncthreads();

        // O += P @ V
        #pragma unroll 4
        for (int k = 0; k < 64; ++k) {
            float a0 = Ps[(ty * 4 + 0) * 64 + k];
            float a1 = Ps[(ty * 4 + 1) * 64 + k];
            float a2 = Ps[(ty * 4 + 2) * 64 + k];
            float a3 = Ps[(ty * 4 + 3) * 64 + k];
            const float* vd = &KVs[k * 64 + tx * 4];
            float b0 = vd[0], b1 = vd[1], b2 = vd[2], b3 = vd[3];
            acc[0][0] += a0 * b0; acc[0][1] += a0 * b1; acc[0][2] += a0 * b2; acc[0][3] += a0 * b3;
            acc[1][0] += a1 * b0; acc[1][1] += a1 * b1; acc[1][2] += a1 * b2; acc[1][3] += a1 * b3;
            acc[2][0] += a2 * b0; acc[2][1] += a2 * b1; acc[2][2] += a2 * b2; acc[2][3] += a2 * b3;
            acc[3][0] += a3 * b0; acc[3][1] += a3 * b1; acc[3][2] += a3 * b2; acc[3][3] += a3 * b3;
        }
    }

    #pragma unroll
    for (int i = 0; i < 4; ++i) {
        float inv = 1.0f / l[i];
        float* op = O + base + (size_t)(qt * 64 + ty * 4 + i) * DMODEL + tx * 4;
        op[0] = acc[i][0] * inv;
        op[1] = acc[i][1] * inv;
        op[2] = acc[i][2] * inv;
        op[3] = acc[i][3] * inv;
    }
}

// ---------------- launch -------------------------------------------
static float* sym_addr(const void* sym) {
    void* p = nullptr;
    cudaGetSymbolAddress(&p, sym);
    return (float*)p;
}

extern "C" void kernel_launch(void* const* d_in, const int* in_sizes, int n_in,
                              void* d_out, int out_size) {
    const float* x     = (const float*)d_in[0];
    const float* ln1_g = (const float*)d_in[1];
    const float* ln1_b = (const float*)d_in[2];
    const float* Wq    = (const float*)d_in[3];
    const float* Wk    = (const float*)d_in[4];
    const float* Wv    = (const float*)d_in[5];
    const float* Wo    = (const float*)d_in[6];
    const float* ln2_g = (const float*)d_in[7];
    const float* ln2_b = (const float*)d_in[8];
    const float* W1    = (const float*)d_in[9];
    const float* b1    = (const float*)d_in[10];
    const float* W2    = (const float*)d_in[11];
    const float* b2    = (const float*)d_in[12];
    float* out = (float*)d_out;

    float* ln  = sym_addr(g_ln);
    float* q   = sym_addr(g_q);
    float* k   = sym_addr(g_k);
    float* v   = sym_addr(g_v);
    float* ctx = sym_addr(g_ctx);
    float* x2  = sym_addr(g_x2);
    float* ff  = sym_addr(g_ff);

    dim3 blk(256);
    dim3 g1k(DMODEL / 128, MROWS / 128);      // N=1024
    dim3 g2k(2 * DMODEL / 128, MROWS / 128);  // N=2048

    // LN1
    ln_kernel<<<MROWS, blk>>>(x, ln1_g, ln1_b, ln);
    // QKV projections
    sgemm_kernel<0, 0, 0><<<g1k, blk>>>(ln, Wq, nullptr, nullptr, q, MROWS, DMODEL, DMODEL);
    sgemm_kernel<0, 0, 0><<<g1k, blk>>>(ln, Wk, nullptr, nullptr, k, MROWS, DMODEL, DMODEL);
    sgemm_kernel<0, 0, 0><<<g1k, blk>>>(ln, Wv, nullptr, nullptr, v, MROWS, DMODEL, DMODEL);
    // attention
    attn_kernel<<<dim3(32, 32), blk>>>(q, k, v, ctx);
    // output projection + residual(x)
    sgemm_kernel<0, 0, 1><<<g1k, blk>>>(ctx, Wo, nullptr, x, x2, MROWS, DMODEL, DMODEL);
    // LN2
    ln_kernel<<<MROWS, blk>>>(x2, ln2_g, ln2_b, ln);
    // FFN up + GELU
    sgemm_kernel<1, 1, 0><<<g2k, blk>>>(ln, W1, b1, nullptr, ff, MROWS, 2 * DMODEL, DMODEL);
    // FFN down + bias + residual(x2) -> out
    sgemm_kernel<0, 1, 1><<<g1k, blk>>>(ff, W2, b2, x2, out, MROWS, DMODEL, 2 * DMODEL);
}

// round 5
// speedup vs baseline: 1.6671x; 1.6671x over previous
#include <cuda_runtime.h>
#include <cuda_bf16.h>
#include <math.h>
#include <stdint.h>

#define DMODEL 1024
#define SEQT   2048
#define BATCH  2
#define MROWS  4096   // BATCH * SEQT
#define NHEAD  16
#define HDIM   64

// ---------------- scratch (static device allocations) ----------------
__device__ float g_ln [MROWS * DMODEL];
__device__ float g_q  [MROWS * DMODEL];
__device__ float g_k  [MROWS * DMODEL];
__device__ float g_v  [MROWS * DMODEL];
__device__ float g_ctx[MROWS * DMODEL];
__device__ float g_x2 [MROWS * DMODEL];
__device__ float g_ff [MROWS * 2 * DMODEL];

// transposed + split weights: [N][K] bf16 hi/lo
__device__ __nv_bfloat16 g_Bq_h[DMODEL * DMODEL], g_Bq_l[DMODEL * DMODEL];
__device__ __nv_bfloat16 g_Bk_h[DMODEL * DMODEL], g_Bk_l[DMODEL * DMODEL];
__device__ __nv_bfloat16 g_Bv_h[DMODEL * DMODEL], g_Bv_l[DMODEL * DMODEL];
__device__ __nv_bfloat16 g_Bo_h[DMODEL * DMODEL], g_Bo_l[DMODEL * DMODEL];
__device__ __nv_bfloat16 g_B1_h[2 * DMODEL * DMODEL], g_B1_l[2 * DMODEL * DMODEL];
__device__ __nv_bfloat16 g_B2_h[2 * DMODEL * DMODEL], g_B2_l[2 * DMODEL * DMODEL];

// ---------------- helpers --------------------------------------------
__device__ __forceinline__ uint32_t smem_u32(const void* p) {
    uint32_t a;
    asm("{ .reg .u64 t; cvta.to.shared.u64 t, %1; cvt.u32.u64 %0, t; }"
        : "=r"(a) : "l"(p));
    return a;
}
__device__ __forceinline__ float gelu_exact(float x) {
    return 0.5f * x * (1.0f + erff(x * 0.70710678118654752f));
}

#define LDM_X4(r0, r1, r2, r3, addr) \
    asm volatile("ldmatrix.sync.aligned.m8n8.x4.shared.b16 {%0,%1,%2,%3}, [%4];" \
        : "=r"(r0), "=r"(r1), "=r"(r2), "=r"(r3) : "r"(addr))

#define MMA16816(d, a, b0, b1) \
    asm volatile("mma.sync.aligned.m16n8k16.row.col.f32.bf16.bf16.f32 " \
        "{%0,%1,%2,%3}, {%4,%5,%6,%7}, {%8,%9}, {%0,%1,%2,%3};" \
        : "+f"((d)[0]), "+f"((d)[1]), "+f"((d)[2]), "+f"((d)[3]) \
        : "r"((a)[0]), "r"((a)[1]), "r"((a)[2]), "r"((a)[3]), \
          "r"(b0), "r"(b1))

// ---------------- weight prep: transpose [K,N] -> [N,K], split bf16 --
__global__ void __launch_bounds__(256) wsplit_kernel(
    const float* __restrict__ W, __nv_bfloat16* __restrict__ Th,
    __nv_bfloat16* __restrict__ Tl, int K, int N) {
    __shared__ float t[32][33];
    int k0 = blockIdx.x * 32, n0 = blockIdx.y * 32;
    int tx = threadIdx.x & 31, ty = threadIdx.x >> 5;  // ty 0..7
    #pragma unroll
    for (int i = 0; i < 4; ++i)
        t[ty + i * 8][tx] = W[(size_t)(k0 + ty + i * 8) * N + n0 + tx];
    __syncthreads();
    #pragma unroll
    for (int i = 0; i < 4; ++i) {
        int n = n0 + ty + i * 8, k = k0 + tx;
        float x = t[tx][ty + i * 8];
        __nv_bfloat16 h = __float2bfloat16_rn(x);
        float lo = x - __bfloat162float(h);
        Th[(size_t)n * K + k] = h;
        Tl[(size_t)n * K + k] = __float2bfloat16_rn(lo);
    }
}

// ---------------- LayerNorm ------------------------------------------
__global__ void __launch_bounds__(256) ln_kernel(const float* __restrict__ x,
                                                 const float* __restrict__ g,
                                                 const float* __restrict__ b,
                                                 float* __restrict__ out) {
    int row = blockIdx.x;
    int tid = threadIdx.x;
    const float4* xr = (const float4*)(x + (size_t)row * DMODEL);
    float4 v = xr[tid];
    float s  = v.x + v.y + v.z + v.w;
    float ss = v.x * v.x + v.y * v.y + v.z * v.z + v.w * v.w;
    #pragma unroll
    for (int o = 16; o > 0; o >>= 1) {
        s  += __shfl_xor_sync(0xffffffffu, s,  o);
        ss += __shfl_xor_sync(0xffffffffu, ss, o);
    }
    __shared__ float sh[16];
    int w = tid >> 5;
    if ((tid & 31) == 0) { sh[w] = s; sh[8 + w] = ss; }
    __syncthreads();
    if (tid < 32) {
        float a  = (tid < 8) ? sh[tid]     : 0.0f;
        float a2 = (tid < 8) ? sh[8 + tid] : 0.0f;
        #pragma unroll
        for (int o = 4; o > 0; o >>= 1) {
            a  += __shfl_xor_sync(0xffffffffu, a,  o);
            a2 += __shfl_xor_sync(0xffffffffu, a2, o);
        }
        if (tid == 0) { sh[0] = a; sh[1] = a2; }
    }
    __syncthreads();
    float mean = sh[0] * (1.0f / DMODEL);
    float var  = sh[1] * (1.0f / DMODEL) - mean * mean;
    float rstd = rsqrtf(var + 1e-5f);
    float4 gg = ((const float4*)g)[tid];
    float4 bb = ((const float4*)b)[tid];
    float4 o4;
    o4.x = (v.x - mean) * rstd * gg.x + bb.x;
    o4.y = (v.y - mean) * rstd * gg.y + bb.y;
    o4.z = (v.z - mean) * rstd * gg.z + bb.z;
    o4.w = (v.w - mean) * rstd * gg.w + bb.w;
    ((float4*)(out + (size_t)row * DMODEL))[tid] = o4;
}

// ---------------- HMMA GEMM: mma.sync bf16 split-precision -----------
// C[M,N] = A[M,K] @ W, with Bh/Bl = bf16 hi/lo split of W^T in [N,K].
// CTA: 128 threads = 4 warps (2m x 2n). CTA tile 128(M) x 64(N), Kc=32.
// Warp tile 64x32: 4 m16-frags x 4 n8-frags. 3 products: AhBh+AlBh+AhBl.
// smem rows padded to 40 bf16 (80B stride -> conflict-free ldmatrix).
#define HG_SMEM_BYTES ((128 * 40 * 2 + 64 * 40 * 2) * 2)  // 30720

template <int GELU, int HAS_BIAS, int HAS_RES>
__global__ void __launch_bounds__(128) hgemm_kernel(
    const float* __restrict__ A, const __nv_bfloat16* __restrict__ Bh,
    const __nv_bfloat16* __restrict__ Bl, const float* __restrict__ bias,
    const float* __restrict__ res, float* __restrict__ C,
    int M, int N, int K) {
    extern __shared__ __align__(16) char smem[];
    __nv_bfloat16* sAh = (__nv_bfloat16*)smem;   // [128][40]
    __nv_bfloat16* sAl = sAh + 128 * 40;
    __nv_bfloat16* sBh = sAl + 128 * 40;          // [64][40]
    __nv_bfloat16* sBl = sBh + 64 * 40;

    int tid = threadIdx.x;
    int lane = tid & 31, wid = tid >> 5;
    int wm = wid >> 1, wn = wid & 1;
    int bm = blockIdx.y * 128, bn = blockIdx.x * 64;

    float acc[4][4][4];
    #pragma unroll
    for (int i = 0; i < 4; ++i)
        #pragma unroll
        for (int j = 0; j < 4; ++j)
            #pragma unroll
            for (int k = 0; k < 4; ++k) acc[i][j][k] = 0.0f;

    uint32_t uAh = smem_u32(sAh), uAl = smem_u32(sAl);
    uint32_t uBh = smem_u32(sBh), uBl = smem_u32(sBl);

    int q = lane >> 3, rr = lane & 7;
    // ldmatrix per-thread source rows/cols (element units)
    int a_row = wm * 64 + (q & 1) * 8 + rr;   // + mi*16
    int a_col = (q >> 1) * 8;                  // + ks*16
    int b_row = wn * 32 + (q >> 1) * 8 + rr;  // + j2*16
    int b_col = (q & 1) * 8;                   // + ks*16

    const int NC = K >> 5;
    for (int c = 0; c < NC; ++c) {
        int kc = c << 5;
        // A: 128 rows x 32 cols fp32 -> bf16 hi/lo
        #pragma unroll
        for (int i = 0; i < 8; ++i) {
            int f = tid + i * 128;
            int r = f >> 3, c4 = (f & 7) << 2;
            float4 v = *(const float4*)&A[(size_t)(bm + r) * K + kc + c4];
            __nv_bfloat162 h0 = __float22bfloat162_rn(make_float2(v.x, v.y));
            __nv_bfloat162 h1 = __float22bfloat162_rn(make_float2(v.z, v.w));
            float2 f0 = __bfloat1622float2(h0);
            float2 f1 = __bfloat1622float2(h1);
            __nv_bfloat162 l0 = __float22bfloat162_rn(make_float2(v.x - f0.x, v.y - f0.y));
            __nv_bfloat162 l1 = __float22bfloat162_rn(make_float2(v.z - f1.x, v.w - f1.y));
            uint2 hh, ll;
            hh.x = *(uint32_t*)&h0; hh.y = *(uint32_t*)&h1;
            ll.x = *(uint32_t*)&l0; ll.y = *(uint32_t*)&l1;
            *(uint2*)&sAh[r * 40 + c4] = hh;
            *(uint2*)&sAl[r * 40 + c4] = ll;
        }
        // B: 64 rows x 32 cols bf16 hi/lo (pre-split)
        #pragma unroll
        for (int i = 0; i < 2; ++i) {
            int u = tid + i * 128;
            int r = u >> 2, c8 = (u & 3) << 3;
            *(uint4*)&sBh[r * 40 + c8] =
                *(const uint4*)&Bh[(size_t)(bn + r) * K + kc + c8];
            *(uint4*)&sBl[r * 40 + c8] =
                *(const uint4*)&Bl[(size_t)(bn + r) * K + kc + c8];
        }
        __syncthreads();

        #pragma unroll
        for (int ks = 0; ks < 2; ++ks) {
            uint32_t ah[4][4], al[4][4], bh[4][2], bl[4][2];
            #pragma unroll
            for (int mi = 0; mi < 4; ++mi) {
                uint32_t off = (uint32_t)((a_row + mi * 16) * 40 + a_col + ks * 16) * 2;
                LDM_X4(ah[mi][0], ah[mi][1], ah[mi][2], ah[mi][3], uAh + off);
                LDM_X4(al[mi][0], al[mi][1], al[mi][2], al[mi][3], uAl + off);
            }
            #pragma unroll
            for (int j2 = 0; j2 < 2; ++j2) {
                uint32_t off = (uint32_t)((b_row + j2 * 16) * 40 + b_col + ks * 16) * 2;
                LDM_X4(bh[2 * j2][0], bh[2 * j2][1], bh[2 * j2 + 1][0], bh[2 * j2 + 1][1],
                       uBh + off);
                LDM_X4(bl[2 * j2][0], bl[2 * j2][1], bl[2 * j2 + 1][0], bl[2 * j2 + 1][1],
                       uBl + off);
            }
            #pragma unroll
            for (int mi = 0; mi < 4; ++mi)
                #pragma unroll
                for (int ni = 0; ni < 4; ++ni) {
                    MMA16816(acc[mi][ni], ah[mi], bh[ni][0], bh[ni][1]);
                    MMA16816(acc[mi][ni], al[mi], bh[ni][0], bh[ni][1]);
                    MMA16816(acc[mi][ni], ah[mi], bl[ni][0], bl[ni][1]);
                }
        }
        __syncthreads();
    }

    // epilogue: register frags -> gmem with fused bias/gelu/residual
    int gid = lane >> 2, tig = lane & 3;
    #pragma unroll
    for (int mi = 0; mi < 4; ++mi) {
        #pragma unroll
        for (int ni = 0; ni < 4; ++ni) {
            int row0 = bm + wm * 64 + mi * 16 + gid;
            int col  = bn + wn * 32 + ni * 8 + tig * 2;
            float c0 = acc[mi][ni][0], c1 = acc[mi][ni][1];
            float c2 = acc[mi][ni][2], c3 = acc[mi][ni][3];
            if (HAS_BIAS) {
                float b0 = bias[col], b1v = bias[col + 1];
                c0 += b0; c1 += b1v; c2 += b0; c3 += b1v;
            }
            if (GELU) {
                c0 = gelu_exact(c0); c1 = gelu_exact(c1);
                c2 = gelu_exact(c2); c3 = gelu_exact(c3);
            }
            if (HAS_RES) {
                float2 r0 = *(const float2*)&res[(size_t)row0 * N + col];
                float2 r1 = *(const float2*)&res[(size_t)(row0 + 8) * N + col];
                c0 += r0.x; c1 += r0.y; c2 += r1.x; c3 += r1.y;
            }
            float2 o0; o0.x = c0; o0.y = c1;
            float2 o1; o1.x = c2; o1.y = c3;
            *(float2*)&C[(size_t)row0 * N + col] = o0;
            *(float2*)&C[(size_t)(row0 + 8) * N + col] = o1;
        }
    }
}

// ---------------- Flash attention (fp32, proven) ---------------------
__global__ void __launch_bounds__(256) attn_kernel(
    const float* __restrict__ Q, const float* __restrict__ K,
    const float* __restrict__ V, float* __restrict__ O) {
    __shared__ float Qs [64 * 64];
    __shared__ float KVs[64 * 64];
    __shared__ float Ps [64 * 64];

    int qt = 31 - (int)blockIdx.x;
    int bh = blockIdx.y;
    int b = bh >> 4, h = bh & 15;
    int tid = threadIdx.x;
    int tx = tid & 15, ty = tid >> 4;

    size_t base = ((size_t)b * SEQT) * DMODEL + (size_t)h * HDIM;

    #pragma unroll
    for (int r = 0; r < 16; ++r) {
        int idx = r * 256 + tid;
        int qr = idx >> 6, d = idx & 63;
        Qs[qr * 64 + d] = Q[base + (size_t)(qt * 64 + qr) * DMODEL + d] * 0.125f;
    }

    float m[4], l[4], acc[4][4];
    #pragma unroll
    for (int i = 0; i < 4; ++i) {
        m[i] = -1e30f; l[i] = 0.0f;
        #pragma unroll
        for (int j = 0; j < 4; ++j) acc[i][j] = 0.0f;
    }

    for (int kt = 0; kt <= qt; ++kt) {
        __syncthreads();
        #pragma unroll
        for (int r = 0; r < 16; ++r) {
            int idx = r * 256 + tid;
            int kr = idx >> 6, d = idx & 63;
            KVs[d * 64 + (kr ^ (d & 31))] =
                K[base + (size_t)(kt * 64 + kr) * DMODEL + d];
        }
        __syncthreads();

        float s[4][4];
        #pragma unroll
        for (int i = 0; i < 4; ++i)
            #pragma unroll
            for (int j = 0; j < 4; ++j) s[i][j] = 0.0f;

        #pragma unroll 4
        for (int d = 0; d < 64; ++d) {
            int c = d & 31;
            float a0 = Qs[(ty * 4 + 0) * 64 + d];
            float a1 = Qs[(ty * 4 + 1) * 64 + d];
            float a2 = Qs[(ty * 4 + 2) * 64 + d];
            float a3 = Qs[(ty * 4 + 3) * 64 + d];
            const float* kd = &KVs[d * 64];
            float b0 = kd[(tx * 4 + 0) ^ c];
            float b1 = kd[(tx * 4 + 1) ^ c];
            float b2 = kd[(tx * 4 + 2) ^ c];
            float b3 = kd[(tx * 4 + 3) ^ c];
            s[0][0] += a0 * b0; s[0][1] += a0 * b1; s[0][2] += a0 * b2; s[0][3] += a0 * b3;
            s[1][0] += a1 * b0; s[1][1] += a1 * b1; s[1][2] += a1 * b2; s[1][3] += a1 * b3;
            s[2][0] += a2 * b0; s[2][1] += a2 * b1; s[2][2] += a2 * b2; s[2][3] += a2 * b3;
            s[3][0] += a3 * b0; s[3][1] += a3 * b1; s[3][2] += a3 * b2; s[3][3] += a3 * b3;
        }

        if (kt == qt) {
            #pragma unroll
            for (int i = 0; i < 4; ++i)
                #pragma unroll
                for (int j = 0; j < 4; ++j)
                    if (tx * 4 + j > ty * 4 + i) s[i][j] = -1e30f;
        }

        #pragma unroll
        for (int i = 0; i < 4; ++i) {
            float t = fmaxf(fmaxf(s[i][0], s[i][1]), fmaxf(s[i][2], s[i][3]));
            #pragma unroll
            for (int o = 1; o < 16; o <<= 1)
                t = fmaxf(t, __shfl_xor_sync(0xffffffffu, t, o));
            float mn = fmaxf(m[i], t);
            float p0 = __expf(s[i][0] - mn);
            float p1 = __expf(s[i][1] - mn);
            float p2 = __expf(s[i][2] - mn);
            float p3 = __expf(s[i][3] - mn);
            float* pr = &Ps[(ty * 4 + i) * 64 + tx * 4];
            pr[0] = p0; pr[1] = p1; pr[2] = p2; pr[3] = p3;
            float su = p0 + p1 + p2 + p3;
            #pragma unroll
            for (int o = 1; o < 16; o <<= 1)
                su += __shfl_xor_sync(0xffffffffu, su, o);
            float alpha = __expf(m[i] - mn);
            l[i] = l[i] * alpha + su;
            acc[i][0] *= alpha; acc[i][1] *= alpha;
            acc[i][2] *= alpha; acc[i][3] *= alpha;
            m[i] = mn;
        }
        __syncthreads();

        #pragma unroll
        for (int r = 0; r < 16; ++r) {
            int idx = r * 256 + tid;
            int kr = idx >> 6, d = idx & 63;
            KVs[kr * 64 + d] = V[base + (size_t)(kt * 64 + kr) * DMODEL + d];
        }
        __syncthreads();

        #pragma unroll 4
        for (int k = 0; k < 64; ++k) {
            float a0 = Ps[(ty * 4 + 0) * 64 + k];
            float a1 = Ps[(ty * 4 + 1) * 64 + k];
            float a2 = Ps[(ty * 4 + 2) * 64 + k];
            float a3 = Ps[(ty * 4 + 3) * 64 + k];
            const float* vd = &KVs[k * 64 + tx * 4];
            float b0 = vd[0], b1 = vd[1], b2 = vd[2], b3 = vd[3];
            acc[0][0] += a0 * b0; acc[0][1] += a0 * b1; acc[0][2] += a0 * b2; acc[0][3] += a0 * b3;
            acc[1][0] += a1 * b0; acc[1][1] += a1 * b1; acc[1][2] += a1 * b2; acc[1][3] += a1 * b3;
            acc[2][0] += a2 * b0; acc[2][1] += a2 * b1; acc[2][2] += a2 * b2; acc[2][3] += a2 * b3;
            acc[3][0] += a3 * b0; acc[3][1] += a3 * b1; acc[3][2] += a3 * b2; acc[3][3] += a3 * b3;
        }
    }

    #pragma unroll
    for (int i = 0; i < 4; ++i) {
        float inv = 1.0f / l[i];
        float* op = O + base + (size_t)(qt * 64 + ty * 4 + i) * DMODEL + tx * 4;
        op[0] = acc[i][0] * inv;
        op[1] = acc[i][1] * inv;
        op[2] = acc[i][2] * inv;
        op[3] = acc[i][3] * inv;
    }
}

// ---------------- launch -------------------------------------------
static void* sym_addr(const void* sym) {
    void* p = nullptr;
    cudaGetSymbolAddress(&p, sym);
    return p;
}

extern "C" void kernel_launch(void* const* d_in, const int* in_sizes, int n_in,
                              void* d_out, int out_size) {
    const float* x     = (const float*)d_in[0];
    const float* ln1_g = (const float*)d_in[1];
    const float* ln1_b = (const float*)d_in[2];
    const float* Wq    = (const float*)d_in[3];
    const float* Wk    = (const float*)d_in[4];
    const float* Wv    = (const float*)d_in[5];
    const float* Wo    = (const float*)d_in[6];
    const float* ln2_g = (const float*)d_in[7];
    const float* ln2_b = (const float*)d_in[8];
    const float* W1    = (const float*)d_in[9];
    const float* b1    = (const float*)d_in[10];
    const float* W2    = (const float*)d_in[11];
    const float* b2    = (const float*)d_in[12];
    float* out = (float*)d_out;

    float* ln  = (float*)sym_addr(g_ln);
    float* q   = (float*)sym_addr(g_q);
    float* k   = (float*)sym_addr(g_k);
    float* v   = (float*)sym_addr(g_v);
    float* ctx = (float*)sym_addr(g_ctx);
    float* x2  = (float*)sym_addr(g_x2);
    float* ff  = (float*)sym_addr(g_ff);

    __nv_bfloat16* Bq_h = (__nv_bfloat16*)sym_addr(g_Bq_h);
    __nv_bfloat16* Bq_l = (__nv_bfloat16*)sym_addr(g_Bq_l);
    __nv_bfloat16* Bk_h = (__nv_bfloat16*)sym_addr(g_Bk_h);
    __nv_bfloat16* Bk_l = (__nv_bfloat16*)sym_addr(g_Bk_l);
    __nv_bfloat16* Bv_h = (__nv_bfloat16*)sym_addr(g_Bv_h);
    __nv_bfloat16* Bv_l = (__nv_bfloat16*)sym_addr(g_Bv_l);
    __nv_bfloat16* Bo_h = (__nv_bfloat16*)sym_addr(g_Bo_h);
    __nv_bfloat16* Bo_l = (__nv_bfloat16*)sym_addr(g_Bo_l);
    __nv_bfloat16* B1_h = (__nv_bfloat16*)sym_addr(g_B1_h);
    __nv_bfloat16* B1_l = (__nv_bfloat16*)sym_addr(g_B1_l);
    __nv_bfloat16* B2_h = (__nv_bfloat16*)sym_addr(g_B2_h);
    __nv_bfloat16* B2_l = (__nv_bfloat16*)sym_addr(g_B2_l);

    dim3 blk128(128), blk256(256);
    dim3 gw(DMODEL / 32, DMODEL / 32);
    dim3 gw1(DMODEL / 32, 2 * DMODEL / 32);
    dim3 gw2(2 * DMODEL / 32, DMODEL / 32);

    // weight prep (transpose + bf16 hi/lo split)
    wsplit_kernel<<<gw,  blk256>>>(Wq, Bq_h, Bq_l, DMODEL, DMODEL);
    wsplit_kernel<<<gw,  blk256>>>(Wk, Bk_h, Bk_l, DMODEL, DMODEL);
    wsplit_kernel<<<gw,  blk256>>>(Wv, Bv_h, Bv_l, DMODEL, DMODEL);
    wsplit_kernel<<<gw,  blk256>>>(Wo, Bo_h, Bo_l, DMODEL, DMODEL);
    wsplit_kernel<<<gw1, blk256>>>(W1, B1_h, B1_l, DMODEL, 2 * DMODEL);
    wsplit_kernel<<<gw2, blk256>>>(W2, B2_h, B2_l, 2 * DMODEL, DMODEL);

    dim3 g1k(DMODEL / 64, MROWS / 128);        // N=1024: (16, 32)
    dim3 g2k(2 * DMODEL / 64, MROWS / 128);    // N=2048: (32, 32)

    // LN1
    ln_kernel<<<MROWS, blk256>>>(x, ln1_g, ln1_b, ln);
    // QKV projections (HMMA split-bf16)
    hgemm_kernel<0, 0, 0><<<g1k, blk128, HG_SMEM_BYTES>>>(
        ln, Bq_h, Bq_l, nullptr, nullptr, q, MROWS, DMODEL, DMODEL);
    hgemm_kernel<0, 0, 0><<<g1k, blk128, HG_SMEM_BYTES>>>(
        ln, Bk_h, Bk_l, nullptr, nullptr, k, MROWS, DMODEL, DMODEL);
    hgemm_kernel<0, 0, 0><<<g1k, blk128, HG_SMEM_BYTES>>>(
        ln, Bv_h, Bv_l, nullptr, nullptr, v, MROWS, DMODEL, DMODEL);
    // attention
    attn_kernel<<<dim3(32, 32), blk256>>>(q, k, v, ctx);
    // output projection + residual(x)
    hgemm_kernel<0, 0, 1><<<g1k, blk128, HG_SMEM_BYTES>>>(
        ctx, Bo_h, Bo_l, nullptr, x, x2, MROWS, DMODEL, DMODEL);
    // LN2
    ln_kernel<<<MROWS, blk256>>>(x2, ln2_g, ln2_b, ln);
    // FFN up + bias + GELU
    hgemm_kernel<1, 1, 0><<<g2k, blk128, HG_SMEM_BYTES>>>(
        ln, B1_h, B1_l, b1, nullptr, ff, MROWS, 2 * DMODEL, DMODEL);
    // FFN down + bias + residual(x2) -> out
    hgemm_kernel<0, 1, 1><<<g1k, blk128, HG_SMEM_BYTES>>>(
        ff, B2_h, B2_l, b2, x2, out, MROWS, DMODEL, 2 * DMODEL);
}

// round 6
// speedup vs baseline: 1.6940x; 1.0161x over previous
#include <cuda_runtime.h>
#include <cuda_bf16.h>
#include <math.h>
#include <stdint.h>

#define DMODEL 1024
#define SEQT   2048
#define BATCH  2
#define MROWS  4096   // BATCH * SEQT
#define NHEAD  16
#define HDIM   64

// ---------------- scratch (static device allocations) ----------------
__device__ float g_q  [MROWS * DMODEL];
__device__ float g_k  [MROWS * DMODEL];
__device__ float g_v  [MROWS * DMODEL];
__device__ float g_x2 [MROWS * DMODEL];
// bf16 hi/lo split activations
__device__ __nv_bfloat16 g_lnh [MROWS * DMODEL], g_lnl [MROWS * DMODEL];
__device__ __nv_bfloat16 g_ctxh[MROWS * DMODEL], g_ctxl[MROWS * DMODEL];
__device__ __nv_bfloat16 g_ffh [MROWS * 2 * DMODEL], g_ffl [MROWS * 2 * DMODEL];

// transposed + split weights: [N][K] bf16 hi/lo
__device__ __nv_bfloat16 g_Bq_h[DMODEL * DMODEL], g_Bq_l[DMODEL * DMODEL];
__device__ __nv_bfloat16 g_Bk_h[DMODEL * DMODEL], g_Bk_l[DMODEL * DMODEL];
__device__ __nv_bfloat16 g_Bv_h[DMODEL * DMODEL], g_Bv_l[DMODEL * DMODEL];
__device__ __nv_bfloat16 g_Bo_h[DMODEL * DMODEL], g_Bo_l[DMODEL * DMODEL];
__device__ __nv_bfloat16 g_B1_h[2 * DMODEL * DMODEL], g_B1_l[2 * DMODEL * DMODEL];
__device__ __nv_bfloat16 g_B2_h[2 * DMODEL * DMODEL], g_B2_l[2 * DMODEL * DMODEL];

// ---------------- helpers --------------------------------------------
__device__ __forceinline__ uint32_t smem_u32(const void* p) {
    uint32_t a;
    asm("{ .reg .u64 t; cvta.to.shared.u64 t, %1; cvt.u32.u64 %0, t; }"
        : "=r"(a) : "l"(p));
    return a;
}
__device__ __forceinline__ float gelu_exact(float x) {
    return 0.5f * x * (1.0f + erff(x * 0.70710678118654752f));
}
// split a float pair into bf16 hi and lo packed u32s
__device__ __forceinline__ void split2(float x, float y, uint32_t& h, uint32_t& l) {
    __nv_bfloat162 hh = __float22bfloat162_rn(make_float2(x, y));
    float2 f = __bfloat1622float2(hh);
    __nv_bfloat162 ll = __float22bfloat162_rn(make_float2(x - f.x, y - f.y));
    h = *(uint32_t*)&hh;
    l = *(uint32_t*)&ll;
}

#define LDM_X4(r0, r1, r2, r3, addr) \
    asm volatile("ldmatrix.sync.aligned.m8n8.x4.shared.b16 {%0,%1,%2,%3}, [%4];" \
        : "=r"(r0), "=r"(r1), "=r"(r2), "=r"(r3) : "r"(addr))

#define MMA16816(d, a, b0, b1) \
    asm volatile("mma.sync.aligned.m16n8k16.row.col.f32.bf16.bf16.f32 " \
        "{%0,%1,%2,%3}, {%4,%5,%6,%7}, {%8,%9}, {%0,%1,%2,%3};" \
        : "+f"((d)[0]), "+f"((d)[1]), "+f"((d)[2]), "+f"((d)[3]) \
        : "r"((a)[0]), "r"((a)[1]), "r"((a)[2]), "r"((a)[3]), \
          "r"(b0), "r"(b1))

#define CP16(dst, src) \
    asm volatile("cp.async.cg.shared.global [%0], [%1], 16;" \
        :: "r"(dst), "l"(src))
#define CP_COMMIT() asm volatile("cp.async.commit_group;")
#define CP_WAIT1()  asm volatile("cp.async.wait_group 1;")
#define CP_WAIT0()  asm volatile("cp.async.wait_group 0;")

// ---------------- weight prep: all 6 weights in ONE launch -----------
// transpose [K,N] -> [N,K], split bf16 hi/lo.
__global__ void __launch_bounds__(256) wsplit_all_kernel(
    const float* __restrict__ Wq, __nv_bfloat16* __restrict__ Bq_h, __nv_bfloat16* __restrict__ Bq_l,
    const float* __restrict__ Wk, __nv_bfloat16* __restrict__ Bk_h, __nv_bfloat16* __restrict__ Bk_l,
    const float* __restrict__ Wv, __nv_bfloat16* __restrict__ Bv_h, __nv_bfloat16* __restrict__ Bv_l,
    const float* __restrict__ Wo, __nv_bfloat16* __restrict__ Bo_h, __nv_bfloat16* __restrict__ Bo_l,
    const float* __restrict__ W1, __nv_bfloat16* __restrict__ B1_h, __nv_bfloat16* __restrict__ B1_l,
    const float* __restrict__ W2, __nv_bfloat16* __restrict__ B2_h, __nv_bfloat16* __restrict__ B2_l) {
    __shared__ float t[32][33];
    int bid = blockIdx.x;
    const float* W;
    __nv_bfloat16 *Th, *Tl;
    int K, N, k0, n0;
    if (bid < 4096) {
        int w = bid >> 10, lb = bid & 1023;
        K = DMODEL; N = DMODEL;
        k0 = (lb & 31) * 32; n0 = (lb >> 5) * 32;
        if (w == 0)      { W = Wq; Th = Bq_h; Tl = Bq_l; }
        else if (w == 1) { W = Wk; Th = Bk_h; Tl = Bk_l; }
        else if (w == 2) { W = Wv; Th = Bv_h; Tl = Bv_l; }
        else             { W = Wo; Th = Bo_h; Tl = Bo_l; }
    } else if (bid < 6144) {
        int lb = bid - 4096;
        K = DMODEL; N = 2 * DMODEL;
        k0 = (lb & 31) * 32; n0 = (lb >> 5) * 32;
        W = W1; Th = B1_h; Tl = B1_l;
    } else {
        int lb = bid - 6144;
        K = 2 * DMODEL; N = DMODEL;
        k0 = (lb & 63) * 32; n0 = (lb >> 6) * 32;
        W = W2; Th = B2_h; Tl = B2_l;
    }
    int tx = threadIdx.x & 31, ty = threadIdx.x >> 5;
    #pragma unroll
    for (int i = 0; i < 4; ++i)
        t[ty + i * 8][tx] = W[(size_t)(k0 + ty + i * 8) * N + n0 + tx];
    __syncthreads();
    #pragma unroll
    for (int i = 0; i < 4; ++i) {
        int n = n0 + ty + i * 8, k = k0 + tx;
        float x = t[tx][ty + i * 8];
        __nv_bfloat16 h = __float2bfloat16_rn(x);
        float lo = x - __bfloat162float(h);
        Th[(size_t)n * K + k] = h;
        Tl[(size_t)n * K + k] = __float2bfloat16_rn(lo);
    }
}

// ---------------- LayerNorm -> bf16 hi/lo ----------------------------
__global__ void __launch_bounds__(256) ln_kernel(const float* __restrict__ x,
                                                 const float* __restrict__ g,
                                                 const float* __restrict__ b,
                                                 __nv_bfloat16* __restrict__ outh,
                                                 __nv_bfloat16* __restrict__ outl) {
    int row = blockIdx.x;
    int tid = threadIdx.x;
    const float4* xr = (const float4*)(x + (size_t)row * DMODEL);
    float4 v = xr[tid];
    float s  = v.x + v.y + v.z + v.w;
    float ss = v.x * v.x + v.y * v.y + v.z * v.z + v.w * v.w;
    #pragma unroll
    for (int o = 16; o > 0; o >>= 1) {
        s  += __shfl_xor_sync(0xffffffffu, s,  o);
        ss += __shfl_xor_sync(0xffffffffu, ss, o);
    }
    __shared__ float sh[16];
    int w = tid >> 5;
    if ((tid & 31) == 0) { sh[w] = s; sh[8 + w] = ss; }
    __syncthreads();
    if (tid < 32) {
        float a  = (tid < 8) ? sh[tid]     : 0.0f;
        float a2 = (tid < 8) ? sh[8 + tid] : 0.0f;
        #pragma unroll
        for (int o = 4; o > 0; o >>= 1) {
            a  += __shfl_xor_sync(0xffffffffu, a,  o);
            a2 += __shfl_xor_sync(0xffffffffu, a2, o);
        }
        if (tid == 0) { sh[0] = a; sh[1] = a2; }
    }
    __syncthreads();
    float mean = sh[0] * (1.0f / DMODEL);
    float var  = sh[1] * (1.0f / DMODEL) - mean * mean;
    float rstd = rsqrtf(var + 1e-5f);
    float4 gg = ((const float4*)g)[tid];
    float4 bb = ((const float4*)b)[tid];
    float o0 = (v.x - mean) * rstd * gg.x + bb.x;
    float o1 = (v.y - mean) * rstd * gg.y + bb.y;
    float o2 = (v.z - mean) * rstd * gg.z + bb.z;
    float o3 = (v.w - mean) * rstd * gg.w + bb.w;
    uint2 h, l;
    split2(o0, o1, h.x, l.x);
    split2(o2, o3, h.y, l.y);
    ((uint2*)(outh + (size_t)row * DMODEL))[tid] = h;
    ((uint2*)(outl + (size_t)row * DMODEL))[tid] = l;
}

// ---------------- HMMA GEMM: cp.async 2-stage pipelined --------------
// C[M,N] = A[M,K] @ W; A pre-split bf16 hi/lo [M][K]; B = W^T split [N][K].
// CTA 128 thr = 4 warps (2m x 2n), tile 128x64, Kc=32, 2 smem stages.
// smem rows padded to 40 bf16 (80B) -> conflict-free ldmatrix.
// stage layout (bytes): Ah 0, Al 10240, Bh 20480, Bl 25600; stage=30720.
#define HG_STAGE  30720
#define HG_SMEM_BYTES (2 * HG_STAGE)

template <int GELU, int HAS_BIAS, int HAS_RES, int OSPLIT>
__global__ void __launch_bounds__(128) hgemm_kernel(
    const __nv_bfloat16* __restrict__ Ah, const __nv_bfloat16* __restrict__ Al,
    const __nv_bfloat16* __restrict__ Bh, const __nv_bfloat16* __restrict__ Bl,
    const float* __restrict__ bias, const float* __restrict__ res,
    float* __restrict__ C, __nv_bfloat16* __restrict__ Ch,
    __nv_bfloat16* __restrict__ Cl, int M, int N, int K) {
    extern __shared__ __align__(16) char smem[];
    uint32_t uS = smem_u32(smem);

    int tid = threadIdx.x;
    int lane = tid & 31, wid = tid >> 5;
    int wm = wid >> 1, wn = wid & 1;
    int bm = blockIdx.y * 128, bn = blockIdx.x * 64;

    float acc[4][4][4];
    #pragma unroll
    for (int i = 0; i < 4; ++i)
        #pragma unroll
        for (int j = 0; j < 4; ++j)
            #pragma unroll
            for (int k = 0; k < 4; ++k) acc[i][j][k] = 0.0f;

    int q = lane >> 3, rr = lane & 7;
    int a_row = wm * 64 + (q & 1) * 8 + rr;
    int a_col = (q >> 1) * 8;
    int b_row = wn * 32 + (q >> 1) * 8 + rr;
    int b_col = (q & 1) * 8;

    // cp.async source indices
    int ar = tid >> 2, ac8 = (tid & 3) << 3;   // + i*32 rows for A
    const int NC = K >> 5;

    auto load_chunk = [&](int c, int s) {
        uint32_t sb = uS + (uint32_t)s * HG_STAGE;
        int kc = c << 5;
        #pragma unroll
        for (int i = 0; i < 4; ++i) {
            int r = ar + i * 32;
            uint32_t d = sb + (uint32_t)(r * 40 + ac8) * 2;
            const __nv_bfloat16* sh_ = Ah + (size_t)(bm + r) * K + kc + ac8;
            const __nv_bfloat16* sl_ = Al + (size_t)(bm + r) * K + kc + ac8;
            CP16(d, sh_);
            CP16(d + 10240, sl_);
        }
        #pragma unroll
        for (int i = 0; i < 2; ++i) {
            int r = ar + i * 32;
            if (r < 64) {
                uint32_t d = sb + 20480 + (uint32_t)(r * 40 + ac8) * 2;
                CP16(d, Bh + (size_t)(bn + r) * K + kc + ac8);
                CP16(d + 5120, Bl + (size_t)(bn + r) * K + kc + ac8);
            }
        }
        CP_COMMIT();
    };

    load_chunk(0, 0);

    for (int c = 0; c < NC; ++c) {
        if (c + 1 < NC) { load_chunk(c + 1, (c + 1) & 1); CP_WAIT1(); }
        else            { CP_WAIT0(); }
        __syncthreads();

        uint32_t sb = uS + (uint32_t)(c & 1) * HG_STAGE;
        #pragma unroll
        for (int ks = 0; ks < 2; ++ks) {
            uint32_t ah[2][4], al[2][4];
            #pragma unroll
            for (int mi = 0; mi < 2; ++mi) {
                // two m16 frags per mi slot handled below via mi2 loop
            }
            // A frags: 4 m16 tiles
            uint32_t ahf[4][4], alf[4][4];
            #pragma unroll
            for (int mi = 0; mi < 4; ++mi) {
                uint32_t off = sb + (uint32_t)((a_row + mi * 16) * 40 + a_col + ks * 16) * 2;
                LDM_X4(ahf[mi][0], ahf[mi][1], ahf[mi][2], ahf[mi][3], off);
                LDM_X4(alf[mi][0], alf[mi][1], alf[mi][2], alf[mi][3], off + 10240);
            }
            #pragma unroll
            for (int j2 = 0; j2 < 2; ++j2) {
                uint32_t bhf[2][2], blf[2][2];
                uint32_t off = sb + 20480 +
                    (uint32_t)((b_row + j2 * 16) * 40 + b_col + ks * 16) * 2;
                LDM_X4(bhf[0][0], bhf[0][1], bhf[1][0], bhf[1][1], off);
                LDM_X4(blf[0][0], blf[0][1], blf[1][0], blf[1][1], off + 5120);
                #pragma unroll
                for (int mi = 0; mi < 4; ++mi)
                    #pragma unroll
                    for (int nj = 0; nj < 2; ++nj) {
                        int ni = j2 * 2 + nj;
                        MMA16816(acc[mi][ni], ahf[mi], bhf[nj][0], bhf[nj][1]);
                        MMA16816(acc[mi][ni], alf[mi], bhf[nj][0], bhf[nj][1]);
                        MMA16816(acc[mi][ni], ahf[mi], blf[nj][0], blf[nj][1]);
                    }
            }
            (void)ah; (void)al;
        }
        __syncthreads();
    }

    // epilogue
    int gid = lane >> 2, tig = lane & 3;
    #pragma unroll
    for (int mi = 0; mi < 4; ++mi) {
        #pragma unroll
        for (int ni = 0; ni < 4; ++ni) {
            int row0 = bm + wm * 64 + mi * 16 + gid;
            int col  = bn + wn * 32 + ni * 8 + tig * 2;
            float c0 = acc[mi][ni][0], c1 = acc[mi][ni][1];
            float c2 = acc[mi][ni][2], c3 = acc[mi][ni][3];
            if (HAS_BIAS) {
                float b0 = bias[col], b1v = bias[col + 1];
                c0 += b0; c1 += b1v; c2 += b0; c3 += b1v;
            }
            if (GELU) {
                c0 = gelu_exact(c0); c1 = gelu_exact(c1);
                c2 = gelu_exact(c2); c3 = gelu_exact(c3);
            }
            if (HAS_RES) {
                float2 r0 = *(const float2*)&res[(size_t)row0 * N + col];
                float2 r1 = *(const float2*)&res[(size_t)(row0 + 8) * N + col];
                c0 += r0.x; c1 += r0.y; c2 += r1.x; c3 += r1.y;
            }
            if (OSPLIT) {
                uint32_t h0, l0, h1, l1;
                split2(c0, c1, h0, l0);
                split2(c2, c3, h1, l1);
                *(uint32_t*)&Ch[(size_t)row0 * N + col] = h0;
                *(uint32_t*)&Cl[(size_t)row0 * N + col] = l0;
                *(uint32_t*)&Ch[(size_t)(row0 + 8) * N + col] = h1;
                *(uint32_t*)&Cl[(size_t)(row0 + 8) * N + col] = l1;
            } else {
                float2 o0; o0.x = c0; o0.y = c1;
                float2 o1; o1.x = c2; o1.y = c3;
                *(float2*)&C[(size_t)row0 * N + col] = o0;
                *(float2*)&C[(size_t)(row0 + 8) * N + col] = o1;
            }
        }
    }
}

// ---------------- Flash attention (fp32) -> ctx bf16 hi/lo -----------
__global__ void __launch_bounds__(256) attn_kernel(
    const float* __restrict__ Q, const float* __restrict__ K,
    const float* __restrict__ V, __nv_bfloat16* __restrict__ Oh,
    __nv_bfloat16* __restrict__ Ol) {
    __shared__ float Qs [64 * 64];
    __shared__ float KVs[64 * 64];
    __shared__ float Ps [64 * 64];

    int qt = 31 - (int)blockIdx.x;
    int bh = blockIdx.y;
    int b = bh >> 4, h = bh & 15;
    int tid = threadIdx.x;
    int tx = tid & 15, ty = tid >> 4;

    size_t base = ((size_t)b * SEQT) * DMODEL + (size_t)h * HDIM;

    #pragma unroll
    for (int r = 0; r < 16; ++r) {
        int idx = r * 256 + tid;
        int qr = idx >> 6, d = idx & 63;
        Qs[qr * 64 + d] = Q[base + (size_t)(qt * 64 + qr) * DMODEL + d] * 0.125f;
    }

    float m[4], l[4], acc[4][4];
    #pragma unroll
    for (int i = 0; i < 4; ++i) {
        m[i] = -1e30f; l[i] = 0.0f;
        #pragma unroll
        for (int j = 0; j < 4; ++j) acc[i][j] = 0.0f;
    }

    for (int kt = 0; kt <= qt; ++kt) {
        __syncthreads();
        #pragma unroll
        for (int r = 0; r < 16; ++r) {
            int idx = r * 256 + tid;
            int kr = idx >> 6, d = idx & 63;
            KVs[d * 64 + (kr ^ (d & 31))] =
                K[base + (size_t)(kt * 64 + kr) * DMODEL + d];
        }
        __syncthreads();

        float s[4][4];
        #pragma unroll
        for (int i = 0; i < 4; ++i)
            #pragma unroll
            for (int j = 0; j < 4; ++j) s[i][j] = 0.0f;

        #pragma unroll 4
        for (int d = 0; d < 64; ++d) {
            int c = d & 31;
            float a0 = Qs[(ty * 4 + 0) * 64 + d];
            float a1 = Qs[(ty * 4 + 1) * 64 + d];
            float a2 = Qs[(ty * 4 + 2) * 64 + d];
            float a3 = Qs[(ty * 4 + 3) * 64 + d];
            const float* kd = &KVs[d * 64];
            float b0 = kd[(tx * 4 + 0) ^ c];
            float b1 = kd[(tx * 4 + 1) ^ c];
            float b2 = kd[(tx * 4 + 2) ^ c];
            float b3 = kd[(tx * 4 + 3) ^ c];
            s[0][0] += a0 * b0; s[0][1] += a0 * b1; s[0][2] += a0 * b2; s[0][3] += a0 * b3;
            s[1][0] += a1 * b0; s[1][1] += a1 * b1; s[1][2] += a1 * b2; s[1][3] += a1 * b3;
            s[2][0] += a2 * b0; s[2][1] += a2 * b1; s[2][2] += a2 * b2; s[2][3] += a2 * b3;
            s[3][0] += a3 * b0; s[3][1] += a3 * b1; s[3][2] += a3 * b2; s[3][3] += a3 * b3;
        }

        if (kt == qt) {
            #pragma unroll
            for (int i = 0; i < 4; ++i)
                #pragma unroll
                for (int j = 0; j < 4; ++j)
                    if (tx * 4 + j > ty * 4 + i) s[i][j] = -1e30f;
        }

        #pragma unroll
        for (int i = 0; i < 4; ++i) {
            float t = fmaxf(fmaxf(s[i][0], s[i][1]), fmaxf(s[i][2], s[i][3]));
            #pragma unroll
            for (int o = 1; o < 16; o <<= 1)
                t = fmaxf(t, __shfl_xor_sync(0xffffffffu, t, o));
            float mn = fmaxf(m[i], t);
            float p0 = __expf(s[i][0] - mn);
            float p1 = __expf(s[i][1] - mn);
            float p2 = __expf(s[i][2] - mn);
            float p3 = __expf(s[i][3] - mn);
            float* pr = &Ps[(ty * 4 + i) * 64 + tx * 4];
            pr[0] = p0; pr[1] = p1; pr[2] = p2; pr[3] = p3;
            float su = p0 + p1 + p2 + p3;
            #pragma unroll
            for (int o = 1; o < 16; o <<= 1)
                su += __shfl_xor_sync(0xffffffffu, su, o);
            float alpha = __expf(m[i] - mn);
            l[i] = l[i] * alpha + su;
            acc[i][0] *= alpha; acc[i][1] *= alpha;
            acc[i][2] *= alpha; acc[i][3] *= alpha;
            m[i] = mn;
        }
        __syncthreads();

        #pragma unroll
        for (int r = 0; r < 16; ++r) {
            int idx = r * 256 + tid;
            int kr = idx >> 6, d = idx & 63;
            KVs[kr * 64 + d] = V[base + (size_t)(kt * 64 + kr) * DMODEL + d];
        }
        __syncthreads();

        #pragma unroll 4
        for (int k = 0; k < 64; ++k) {
            float a0 = Ps[(ty * 4 + 0) * 64 + k];
            float a1 = Ps[(ty * 4 + 1) * 64 + k];
            float a2 = Ps[(ty * 4 + 2) * 64 + k];
            float a3 = Ps[(ty * 4 + 3) * 64 + k];
            const float* vd = &KVs[k * 64 + tx * 4];
            float b0 = vd[0], b1 = vd[1], b2 = vd[2], b3 = vd[3];
            acc[0][0] += a0 * b0; acc[0][1] += a0 * b1; acc[0][2] += a0 * b2; acc[0][3] += a0 * b3;
            acc[1][0] += a1 * b0; acc[1][1] += a1 * b1; acc[1][2] += a1 * b2; acc[1][3] += a1 * b3;
            acc[2][0] += a2 * b0; acc[2][1] += a2 * b1; acc[2][2] += a2 * b2; acc[2][3] += a2 * b3;
            acc[3][0] += a3 * b0; acc[3][1] += a3 * b1; acc[3][2] += a3 * b2; acc[3][3] += a3 * b3;
        }
    }

    #pragma unroll
    for (int i = 0; i < 4; ++i) {
        float inv = 1.0f / l[i];
        float o0 = acc[i][0] * inv, o1 = acc[i][1] * inv;
        float o2 = acc[i][2] * inv, o3 = acc[i][3] * inv;
        uint2 hh, ll;
        split2(o0, o1, hh.x, ll.x);
        split2(o2, o3, hh.y, ll.y);
        size_t idx = base + (size_t)(qt * 64 + ty * 4 + i) * DMODEL + tx * 4;
        *(uint2*)&Oh[idx] = hh;
        *(uint2*)&Ol[idx] = ll;
    }
}

// ---------------- launch -------------------------------------------
static void* sym_addr(const void* sym) {
    void* p = nullptr;
    cudaGetSymbolAddress(&p, sym);
    return p;
}

extern "C" void kernel_launch(void* const* d_in, const int* in_sizes, int n_in,
                              void* d_out, int out_size) {
    const float* x     = (const float*)d_in[0];
    const float* ln1_g = (const float*)d_in[1];
    const float* ln1_b = (const float*)d_in[2];
    const float* Wq    = (const float*)d_in[3];
    const float* Wk    = (const float*)d_in[4];
    const float* Wv    = (const float*)d_in[5];
    const float* Wo    = (const float*)d_in[6];
    const float* ln2_g = (const float*)d_in[7];
    const float* ln2_b = (const float*)d_in[8];
    const float* W1    = (const float*)d_in[9];
    const float* b1    = (const float*)d_in[10];
    const float* W2    = (const float*)d_in[11];
    const float* b2    = (const float*)d_in[12];
    float* out = (float*)d_out;

    float* q   = (float*)sym_addr(g_q);
    float* k   = (float*)sym_addr(g_k);
    float* v   = (float*)sym_addr(g_v);
    float* x2  = (float*)sym_addr(g_x2);
    __nv_bfloat16* lnh  = (__nv_bfloat16*)sym_addr(g_lnh);
    __nv_bfloat16* lnl  = (__nv_bfloat16*)sym_addr(g_lnl);
    __nv_bfloat16* ctxh = (__nv_bfloat16*)sym_addr(g_ctxh);
    __nv_bfloat16* ctxl = (__nv_bfloat16*)sym_addr(g_ctxl);
    __nv_bfloat16* ffh  = (__nv_bfloat16*)sym_addr(g_ffh);
    __nv_bfloat16* ffl  = (__nv_bfloat16*)sym_addr(g_ffl);

    __nv_bfloat16* Bq_h = (__nv_bfloat16*)sym_addr(g_Bq_h);
    __nv_bfloat16* Bq_l = (__nv_bfloat16*)sym_addr(g_Bq_l);
    __nv_bfloat16* Bk_h = (__nv_bfloat16*)sym_addr(g_Bk_h);
    __nv_bfloat16* Bk_l = (__nv_bfloat16*)sym_addr(g_Bk_l);
    __nv_bfloat16* Bv_h = (__nv_bfloat16*)sym_addr(g_Bv_h);
    __nv_bfloat16* Bv_l = (__nv_bfloat16*)sym_addr(g_Bv_l);
    __nv_bfloat16* Bo_h = (__nv_bfloat16*)sym_addr(g_Bo_h);
    __nv_bfloat16* Bo_l = (__nv_bfloat16*)sym_addr(g_Bo_l);
    __nv_bfloat16* B1_h = (__nv_bfloat16*)sym_addr(g_B1_h);
    __nv_bfloat16* B1_l = (__nv_bfloat16*)sym_addr(g_B1_l);
    __nv_bfloat16* B2_h = (__nv_bfloat16*)sym_addr(g_B2_h);
    __nv_bfloat16* B2_l = (__nv_bfloat16*)sym_addr(g_B2_l);

    cudaFuncSetAttribute(hgemm_kernel<0, 0, 0, 0>,
                         cudaFuncAttributeMaxDynamicSharedMemorySize, HG_SMEM_BYTES);
    cudaFuncSetAttribute(hgemm_kernel<0, 0, 1, 0>,
                         cudaFuncAttributeMaxDynamicSharedMemorySize, HG_SMEM_BYTES);
    cudaFuncSetAttribute(hgemm_kernel<1, 1, 0, 1>,
                         cudaFuncAttributeMaxDynamicSharedMemorySize, HG_SMEM_BYTES);
    cudaFuncSetAttribute(hgemm_kernel<0, 1, 1, 0>,
                         cudaFuncAttributeMaxDynamicSharedMemorySize, HG_SMEM_BYTES);

    dim3 blk128(128), blk256(256);
    dim3 g1k(DMODEL / 64, MROWS / 128);        // (16, 32)
    dim3 g2k(2 * DMODEL / 64, MROWS / 128);    // (32, 32)

    // 0: all weight prep in one launch
    wsplit_all_kernel<<<8192, blk256>>>(Wq, Bq_h, Bq_l, Wk, Bk_h, Bk_l,
                                        Wv, Bv_h, Bv_l, Wo, Bo_h, Bo_l,
                                        W1, B1_h, B1_l, W2, B2_h, B2_l);
    // 1: LN1 -> bf16 hi/lo
    ln_kernel<<<MROWS, blk256>>>(x, ln1_g, ln1_b, lnh, lnl);
    // 2-4: QKV projections
    hgemm_kernel<0, 0, 0, 0><<<g1k, blk128, HG_SMEM_BYTES>>>(
        lnh, lnl, Bq_h, Bq_l, nullptr, nullptr, q, nullptr, nullptr,
        MROWS, DMODEL, DMODEL);
    hgemm_kernel<0, 0, 0, 0><<<g1k, blk128, HG_SMEM_BYTES>>>(
        lnh, lnl, Bk_h, Bk_l, nullptr, nullptr, k, nullptr, nullptr,
        MROWS, DMODEL, DMODEL);
    hgemm_kernel<0, 0, 0, 0><<<g1k, blk128, HG_SMEM_BYTES>>>(
        lnh, lnl, Bv_h, Bv_l, nullptr, nullptr, v, nullptr, nullptr,
        MROWS, DMODEL, DMODEL);
    // 5: attention (ncu -s 5 captures this) -> ctx bf16 hi/lo
    attn_kernel<<<dim3(32, 32), blk256>>>(q, k, v, ctxh, ctxl);
    // 6: output projection + residual(x) -> x2 fp32
    hgemm_kernel<0, 0, 1, 0><<<g1k, blk128, HG_SMEM_BYTES>>>(
        ctxh, ctxl, Bo_h, Bo_l, nullptr, x, x2, nullptr, nullptr,
        MROWS, DMODEL, DMODEL);
    // 7: LN2 -> bf16 hi/lo
    ln_kernel<<<MROWS, blk256>>>(x2, ln2_g, ln2_b, lnh, lnl);
    // 8: FFN up + bias + GELU -> ff bf16 hi/lo
    hgemm_kernel<1, 1, 0, 1><<<g2k, blk128, HG_SMEM_BYTES>>>(
        lnh, lnl, B1_h, B1_l, b1, nullptr, nullptr, ffh, ffl,
        MROWS, 2 * DMODEL, DMODEL);
    // 9: FFN down + bias + residual(x2) -> out fp32
    hgemm_kernel<0, 1, 1, 0><<<g1k, blk128, HG_SMEM_BYTES>>>(
        ffh, ffl, B2_h, B2_l, b2, x2, out, nullptr, nullptr,
        MROWS, DMODEL, 2 * DMODEL);
}

// round 8
// speedup vs baseline: 2.6621x; 1.5715x over previous
#include <cuda_runtime.h>
#include <cuda_bf16.h>
#include <math.h>
#include <stdint.h>

#define DMODEL 1024
#define SEQT   2048
#define BATCH  2
#define MROWS  4096   // BATCH * SEQT
#define NHEAD  16
#define HDIM   64

// ---------------- scratch (static device allocations) ----------------
__device__ float g_x2 [MROWS * DMODEL];
// bf16 hi/lo split activations
__device__ __nv_bfloat16 g_lnh [MROWS * DMODEL], g_lnl [MROWS * DMODEL];
__device__ __nv_bfloat16 g_qh  [MROWS * DMODEL], g_ql  [MROWS * DMODEL];
__device__ __nv_bfloat16 g_kh  [MROWS * DMODEL], g_kl  [MROWS * DMODEL];
__device__ __nv_bfloat16 g_vh  [MROWS * DMODEL], g_vl  [MROWS * DMODEL];
__device__ __nv_bfloat16 g_ctxh[MROWS * DMODEL], g_ctxl[MROWS * DMODEL];
__device__ __nv_bfloat16 g_ffh [MROWS * 2 * DMODEL], g_ffl [MROWS * 2 * DMODEL];

// transposed + split weights: [N][K] bf16 hi/lo
__device__ __nv_bfloat16 g_Bq_h[DMODEL * DMODEL], g_Bq_l[DMODEL * DMODEL];
__device__ __nv_bfloat16 g_Bk_h[DMODEL * DMODEL], g_Bk_l[DMODEL * DMODEL];
__device__ __nv_bfloat16 g_Bv_h[DMODEL * DMODEL], g_Bv_l[DMODEL * DMODEL];
__device__ __nv_bfloat16 g_Bo_h[DMODEL * DMODEL], g_Bo_l[DMODEL * DMODEL];
__device__ __nv_bfloat16 g_B1_h[2 * DMODEL * DMODEL], g_B1_l[2 * DMODEL * DMODEL];
__device__ __nv_bfloat16 g_B2_h[2 * DMODEL * DMODEL], g_B2_l[2 * DMODEL * DMODEL];

// ---------------- helpers --------------------------------------------
__device__ __forceinline__ uint32_t smem_u32(const void* p) {
    uint32_t a;
    asm("{ .reg .u64 t; cvta.to.shared.u64 t, %1; cvt.u32.u64 %0, t; }"
        : "=r"(a) : "l"(p));
    return a;
}
__device__ __forceinline__ float gelu_exact(float x) {
    return 0.5f * x * (1.0f + erff(x * 0.70710678118654752f));
}
__device__ __forceinline__ void split2(float x, float y, uint32_t& h, uint32_t& l) {
    __nv_bfloat162 hh = __float22bfloat162_rn(make_float2(x, y));
    float2 f = __bfloat1622float2(hh);
    __nv_bfloat162 ll = __float22bfloat162_rn(make_float2(x - f.x, y - f.y));
    h = *(uint32_t*)&hh;
    l = *(uint32_t*)&ll;
}

#define LDM_X4(r0, r1, r2, r3, addr) \
    asm volatile("ldmatrix.sync.aligned.m8n8.x4.shared.b16 {%0,%1,%2,%3}, [%4];" \
        : "=r"(r0), "=r"(r1), "=r"(r2), "=r"(r3) : "r"(addr))
#define LDM_X4T(r0, r1, r2, r3, addr) \
    asm volatile("ldmatrix.sync.aligned.m8n8.x4.trans.shared.b16 {%0,%1,%2,%3}, [%4];" \
        : "=r"(r0), "=r"(r1), "=r"(r2), "=r"(r3) : "r"(addr))

#define MMA16816(d, a, b0, b1) \
    asm volatile("mma.sync.aligned.m16n8k16.row.col.f32.bf16.bf16.f32 " \
        "{%0,%1,%2,%3}, {%4,%5,%6,%7}, {%8,%9}, {%0,%1,%2,%3};" \
        : "+f"((d)[0]), "+f"((d)[1]), "+f"((d)[2]), "+f"((d)[3]) \
        : "r"((a)[0]), "r"((a)[1]), "r"((a)[2]), "r"((a)[3]), \
          "r"(b0), "r"(b1))

#define CP16(dst, src) \
    asm volatile("cp.async.cg.shared.global [%0], [%1], 16;" \
        :: "r"(dst), "l"(src))
#define CP_COMMIT() asm volatile("cp.async.commit_group;")
#define CP_WAIT1()  asm volatile("cp.async.wait_group 1;")
#define CP_WAIT0()  asm volatile("cp.async.wait_group 0;")

// ---------------- weight prep: all 6 weights in ONE launch -----------
__global__ void __launch_bounds__(256) wsplit_all_kernel(
    const float* __restrict__ Wq, __nv_bfloat16* __restrict__ Bq_h, __nv_bfloat16* __restrict__ Bq_l,
    const float* __restrict__ Wk, __nv_bfloat16* __restrict__ Bk_h, __nv_bfloat16* __restrict__ Bk_l,
    const float* __restrict__ Wv, __nv_bfloat16* __restrict__ Bv_h, __nv_bfloat16* __restrict__ Bv_l,
    const float* __restrict__ Wo, __nv_bfloat16* __restrict__ Bo_h, __nv_bfloat16* __restrict__ Bo_l,
    const float* __restrict__ W1, __nv_bfloat16* __restrict__ B1_h, __nv_bfloat16* __restrict__ B1_l,
    const float* __restrict__ W2, __nv_bfloat16* __restrict__ B2_h, __nv_bfloat16* __restrict__ B2_l) {
    __shared__ float t[32][33];
    int bid = blockIdx.x;
    const float* W;
    __nv_bfloat16 *Th, *Tl;
    int K, N, k0, n0;
    if (bid < 4096) {
        int w = bid >> 10, lb = bid & 1023;
        K = DMODEL; N = DMODEL;
        k0 = (lb & 31) * 32; n0 = (lb >> 5) * 32;
        if (w == 0)      { W = Wq; Th = Bq_h; Tl = Bq_l; }
        else if (w == 1) { W = Wk; Th = Bk_h; Tl = Bk_l; }
        else if (w == 2) { W = Wv; Th = Bv_h; Tl = Bv_l; }
        else             { W = Wo; Th = Bo_h; Tl = Bo_l; }
    } else if (bid < 6144) {
        int lb = bid - 4096;
        K = DMODEL; N = 2 * DMODEL;
        k0 = (lb & 31) * 32; n0 = (lb >> 5) * 32;
        W = W1; Th = B1_h; Tl = B1_l;
    } else {
        int lb = bid - 6144;
        K = 2 * DMODEL; N = DMODEL;
        k0 = (lb & 63) * 32; n0 = (lb >> 6) * 32;
        W = W2; Th = B2_h; Tl = B2_l;
    }
    int tx = threadIdx.x & 31, ty = threadIdx.x >> 5;
    #pragma unroll
    for (int i = 0; i < 4; ++i)
        t[ty + i * 8][tx] = W[(size_t)(k0 + ty + i * 8) * N + n0 + tx];
    __syncthreads();
    #pragma unroll
    for (int i = 0; i < 4; ++i) {
        int n = n0 + ty + i * 8, k = k0 + tx;
        float x = t[tx][ty + i * 8];
        __nv_bfloat16 h = __float2bfloat16_rn(x);
        float lo = x - __bfloat162float(h);
        Th[(size_t)n * K + k] = h;
        Tl[(size_t)n * K + k] = __float2bfloat16_rn(lo);
    }
}

// ---------------- LayerNorm -> bf16 hi/lo ----------------------------
__global__ void __launch_bounds__(256) ln_kernel(const float* __restrict__ x,
                                                 const float* __restrict__ g,
                                                 const float* __restrict__ b,
                                                 __nv_bfloat16* __restrict__ outh,
                                                 __nv_bfloat16* __restrict__ outl) {
    int row = blockIdx.x;
    int tid = threadIdx.x;
    const float4* xr = (const float4*)(x + (size_t)row * DMODEL);
    float4 v = xr[tid];
    float s  = v.x + v.y + v.z + v.w;
    float ss = v.x * v.x + v.y * v.y + v.z * v.z + v.w * v.w;
    #pragma unroll
    for (int o = 16; o > 0; o >>= 1) {
        s  += __shfl_xor_sync(0xffffffffu, s,  o);
        ss += __shfl_xor_sync(0xffffffffu, ss, o);
    }
    __shared__ float sh[16];
    int w = tid >> 5;
    if ((tid & 31) == 0) { sh[w] = s; sh[8 + w] = ss; }
    __syncthreads();
    if (tid < 32) {
        float a  = (tid < 8) ? sh[tid]     : 0.0f;
        float a2 = (tid < 8) ? sh[8 + tid] : 0.0f;
        #pragma unroll
        for (int o = 4; o > 0; o >>= 1) {
            a  += __shfl_xor_sync(0xffffffffu, a,  o);
            a2 += __shfl_xor_sync(0xffffffffu, a2, o);
        }
        if (tid == 0) { sh[0] = a; sh[1] = a2; }
    }
    __syncthreads();
    float mean = sh[0] * (1.0f / DMODEL);
    float var  = sh[1] * (1.0f / DMODEL) - mean * mean;
    float rstd = rsqrtf(var + 1e-5f);
    float4 gg = ((const float4*)g)[tid];
    float4 bb = ((const float4*)b)[tid];
    float o0 = (v.x - mean) * rstd * gg.x + bb.x;
    float o1 = (v.y - mean) * rstd * gg.y + bb.y;
    float o2 = (v.z - mean) * rstd * gg.z + bb.z;
    float o3 = (v.w - mean) * rstd * gg.w + bb.w;
    uint2 h, l;
    split2(o0, o1, h.x, l.x);
    split2(o2, o3, h.y, l.y);
    ((uint2*)(outh + (size_t)row * DMODEL))[tid] = h;
    ((uint2*)(outl + (size_t)row * DMODEL))[tid] = l;
}

// ---------------- HMMA GEMM: cp.async 2-stage pipelined --------------
// PAD 40 elems (80B rows, 16B-aligned for cp.async/ldmatrix):
// stage = A(h,l) 2*10240 + B(h,l) 2*5120 = 30720B; 2 stages -> 3 CTAs/SM.
#define HPAD 40
#define HG_A_L   10240
#define HG_B     20480
#define HG_B_L   5120
#define HG_STAGE 30720
#define HG_SMEM_BYTES (2 * HG_STAGE)

template <int GELU, int HAS_BIAS, int HAS_RES, int OSPLIT>
__global__ void __launch_bounds__(128) hgemm_kernel(
    const __nv_bfloat16* __restrict__ Ah, const __nv_bfloat16* __restrict__ Al,
    const __nv_bfloat16* __restrict__ Bh, const __nv_bfloat16* __restrict__ Bl,
    const float* __restrict__ bias, const float* __restrict__ res,
    float* __restrict__ C, __nv_bfloat16* __restrict__ Ch,
    __nv_bfloat16* __restrict__ Cl, int M, int N, int K) {
    extern __shared__ __align__(16) char smem[];
    uint32_t uS = smem_u32(smem);

    int tid = threadIdx.x;
    int lane = tid & 31, wid = tid >> 5;
    int wm = wid >> 1, wn = wid & 1;
    int bm = blockIdx.y * 128, bn = blockIdx.x * 64;

    float acc[4][4][4];
    #pragma unroll
    for (int i = 0; i < 4; ++i)
        #pragma unroll
        for (int j = 0; j < 4; ++j)
            #pragma unroll
            for (int k = 0; k < 4; ++k) acc[i][j][k] = 0.0f;

    int q = lane >> 3, rr = lane & 7;
    int a_row = wm * 64 + (q & 1) * 8 + rr;
    int a_col = (q >> 1) * 8;
    int b_row = wn * 32 + (q >> 1) * 8 + rr;
    int b_col = (q & 1) * 8;

    int ar = tid >> 2, ac8 = (tid & 3) << 3;
    const int NC = K >> 5;

    auto load_chunk = [&](int c, int s) {
        uint32_t sb = uS + (uint32_t)s * HG_STAGE;
        int kc = c << 5;
        #pragma unroll
        for (int i = 0; i < 4; ++i) {
            int r = ar + i * 32;
            uint32_t d = sb + (uint32_t)(r * HPAD + ac8) * 2;
            CP16(d, Ah + (size_t)(bm + r) * K + kc + ac8);
            CP16(d + HG_A_L, Al + (size_t)(bm + r) * K + kc + ac8);
        }
        #pragma unroll
        for (int i = 0; i < 2; ++i) {
            int r = ar + i * 32;
            uint32_t d = sb + HG_B + (uint32_t)(r * HPAD + ac8) * 2;
            CP16(d, Bh + (size_t)(bn + r) * K + kc + ac8);
            CP16(d + HG_B_L, Bl + (size_t)(bn + r) * K + kc + ac8);
        }
        CP_COMMIT();
    };

    load_chunk(0, 0);

    for (int c = 0; c < NC; ++c) {
        if (c + 1 < NC) { load_chunk(c + 1, (c + 1) & 1); CP_WAIT1(); }
        else            { CP_WAIT0(); }
        __syncthreads();

        uint32_t sb = uS + (uint32_t)(c & 1) * HG_STAGE;
        #pragma unroll
        for (int ks = 0; ks < 2; ++ks) {
            uint32_t ahf[4][4], alf[4][4];
            #pragma unroll
            for (int mi = 0; mi < 4; ++mi) {
                uint32_t off = sb + (uint32_t)((a_row + mi * 16) * HPAD + a_col + ks * 16) * 2;
                LDM_X4(ahf[mi][0], ahf[mi][1], ahf[mi][2], ahf[mi][3], off);
                LDM_X4(alf[mi][0], alf[mi][1], alf[mi][2], alf[mi][3], off + HG_A_L);
            }
            #pragma unroll
            for (int j2 = 0; j2 < 2; ++j2) {
                uint32_t bhf[2][2], blf[2][2];
                uint32_t off = sb + HG_B +
                    (uint32_t)((b_row + j2 * 16) * HPAD + b_col + ks * 16) * 2;
                LDM_X4(bhf[0][0], bhf[0][1], bhf[1][0], bhf[1][1], off);
                LDM_X4(blf[0][0], blf[0][1], blf[1][0], blf[1][1], off + HG_B_L);
                #pragma unroll
                for (int mi = 0; mi < 4; ++mi)
                    #pragma unroll
                    for (int nj = 0; nj < 2; ++nj) {
                        int ni = j2 * 2 + nj;
                        MMA16816(acc[mi][ni], ahf[mi], bhf[nj][0], bhf[nj][1]);
                        MMA16816(acc[mi][ni], alf[mi], bhf[nj][0], bhf[nj][1]);
                        MMA16816(acc[mi][ni], ahf[mi], blf[nj][0], blf[nj][1]);
                    }
            }
        }
        __syncthreads();
    }

    // epilogue
    int gid = lane >> 2, tig = lane & 3;
    #pragma unroll
    for (int mi = 0; mi < 4; ++mi) {
        #pragma unroll
        for (int ni = 0; ni < 4; ++ni) {
            int row0 = bm + wm * 64 + mi * 16 + gid;
            int col  = bn + wn * 32 + ni * 8 + tig * 2;
            float c0 = acc[mi][ni][0], c1 = acc[mi][ni][1];
            float c2 = acc[mi][ni][2], c3 = acc[mi][ni][3];
            if (HAS_BIAS) {
                float b0 = bias[col], b1v = bias[col + 1];
                c0 += b0; c1 += b1v; c2 += b0; c3 += b1v;
            }
            if (GELU) {
                c0 = gelu_exact(c0); c1 = gelu_exact(c1);
                c2 = gelu_exact(c2); c3 = gelu_exact(c3);
            }
            if (HAS_RES) {
                float2 r0 = *(const float2*)&res[(size_t)row0 * N + col];
                float2 r1 = *(const float2*)&res[(size_t)(row0 + 8) * N + col];
                c0 += r0.x; c1 += r0.y; c2 += r1.x; c3 += r1.y;
            }
            if (OSPLIT) {
                uint32_t h0, l0, h1, l1;
                split2(c0, c1, h0, l0);
                split2(c2, c3, h1, l1);
                *(uint32_t*)&Ch[(size_t)row0 * N + col] = h0;
                *(uint32_t*)&Cl[(size_t)row0 * N + col] = l0;
                *(uint32_t*)&Ch[(size_t)(row0 + 8) * N + col] = h1;
                *(uint32_t*)&Cl[(size_t)(row0 + 8) * N + col] = l1;
            } else {
                float2 o0; o0.x = c0; o0.y = c1;
                float2 o1; o1.x = c2; o1.y = c3;
                *(float2*)&C[(size_t)row0 * N + col] = o0;
                *(float2*)&C[(size_t)(row0 + 8) * N + col] = o1;
            }
        }
    }
}

// ---------------- Tensor-core flash attention -------------------------
// CTA 128 thr = 4 warps, tile 64q x 64k, warp = 16 q-rows, full 64 cols.
// S = QK^T and O = P.V via m16n8k16 bf16 3-product split. P stays in regs
// (acc->A-frag repack identity). K/V cp.async double-buffered.
// AT_PAD=72 elems = 144B rows (16B aligned; 144 mod 128 = 16 -> bank-walk
// conflict-free for ldmatrix).
#define AT_PAD   72
#define AT_QL    9216
#define AT_KV    18432
#define AT_TILE  9216
#define AT_STAGE 36864
#define AT_SMEM  (AT_KV + 2 * AT_STAGE)  // 92160

__global__ void __launch_bounds__(128) attn_kernel(
    const __nv_bfloat16* __restrict__ Qh_g, const __nv_bfloat16* __restrict__ Ql_g,
    const __nv_bfloat16* __restrict__ Kh_g, const __nv_bfloat16* __restrict__ Kl_g,
    const __nv_bfloat16* __restrict__ Vh_g, const __nv_bfloat16* __restrict__ Vl_g,
    __nv_bfloat16* __restrict__ Oh, __nv_bfloat16* __restrict__ Ol) {
    extern __shared__ __align__(16) char smem[];
    uint32_t uS = smem_u32(smem);

    int qt = 31 - (int)blockIdx.x;
    int bh = blockIdx.y;
    int b = bh >> 4, h = bh & 15;
    int tid = threadIdx.x, lane = tid & 31, wid = tid >> 5;
    int gid = lane >> 2, tig = lane & 3;
    int q = lane >> 3, rr = lane & 7;

    size_t rowbase = (size_t)b * SEQT;

    auto ld_tile = [&](const __nv_bfloat16* G, uint32_t dst, int trow) {
        #pragma unroll
        for (int i = 0; i < 4; ++i) {
            int idx = tid + i * 128;
            int r = idx >> 3, c8 = (idx & 7) << 3;
            CP16(dst + (uint32_t)(r * AT_PAD + c8) * 2,
                 G + (rowbase + trow + r) * (size_t)DMODEL + h * HDIM + c8);
        }
    };

    // prologue: Q tile + KV tile 0 (group 0)
    ld_tile(Qh_g, uS, qt * 64);
    ld_tile(Ql_g, uS + AT_QL, qt * 64);
    ld_tile(Kh_g, uS + AT_KV, 0);
    ld_tile(Kl_g, uS + AT_KV + AT_TILE, 0);
    ld_tile(Vh_g, uS + AT_KV + 2 * AT_TILE, 0);
    ld_tile(Vl_g, uS + AT_KV + 3 * AT_TILE, 0);
    CP_COMMIT();

    float oacc[8][4];
    #pragma unroll
    for (int i = 0; i < 8; ++i)
        #pragma unroll
        for (int j = 0; j < 4; ++j) oacc[i][j] = 0.0f;
    float m0 = -1e30f, m1 = -1e30f, l0 = 0.0f, l1 = 0.0f;

    int a_row   = wid * 16 + (q & 1) * 8 + rr;
    int a_csel  = (q >> 1) * 8;
    int b_rsel  = (q >> 1) * 8 + rr;   // + j2*16
    int b_csel  = (q & 1) * 8;         // + ks*16
    int v_rsel  = (q & 1) * 8 + rr;    // + ks*16
    int v_csel  = (q >> 1) * 8;        // + j2*16

    for (int kt = 0; kt <= qt; ++kt) {
        uint32_t st = uS + AT_KV + (uint32_t)(kt & 1) * AT_STAGE;
        if (kt < qt) {
            uint32_t s2 = uS + AT_KV + (uint32_t)((kt + 1) & 1) * AT_STAGE;
            ld_tile(Kh_g, s2, (kt + 1) * 64);
            ld_tile(Kl_g, s2 + AT_TILE, (kt + 1) * 64);
            ld_tile(Vh_g, s2 + 2 * AT_TILE, (kt + 1) * 64);
            ld_tile(Vl_g, s2 + 3 * AT_TILE, (kt + 1) * 64);
            CP_COMMIT();
            CP_WAIT1();
        } else {
            CP_WAIT0();
        }
        __syncthreads();

        // ---- S = Q K^T (3-product split) ----
        float sc[8][4];
        #pragma unroll
        for (int i = 0; i < 8; ++i)
            #pragma unroll
            for (int j = 0; j < 4; ++j) sc[i][j] = 0.0f;

        #pragma unroll
        for (int ks = 0; ks < 4; ++ks) {
            uint32_t qhf[4], qlf[4];
            uint32_t aoff = (uint32_t)(a_row * AT_PAD + a_csel + ks * 16) * 2;
            LDM_X4(qhf[0], qhf[1], qhf[2], qhf[3], uS + aoff);
            LDM_X4(qlf[0], qlf[1], qlf[2], qlf[3], uS + AT_QL + aoff);
            #pragma unroll
            for (int j2 = 0; j2 < 4; ++j2) {
                uint32_t kh0, kh1, kh2, kh3, kl0, kl1, kl2, kl3;
                uint32_t boff = st +
                    (uint32_t)((j2 * 16 + b_rsel) * AT_PAD + b_csel + ks * 16) * 2;
                LDM_X4(kh0, kh1, kh2, kh3, boff);
                LDM_X4(kl0, kl1, kl2, kl3, boff + AT_TILE);
                MMA16816(sc[2 * j2],     qhf, kh0, kh1);
                MMA16816(sc[2 * j2],     qlf, kh0, kh1);
                MMA16816(sc[2 * j2],     qhf, kl0, kl1);
                MMA16816(sc[2 * j2 + 1], qhf, kh2, kh3);
                MMA16816(sc[2 * j2 + 1], qlf, kh2, kh3);
                MMA16816(sc[2 * j2 + 1], qhf, kl2, kl3);
            }
        }

        // scale + causal mask
        #pragma unroll
        for (int ni = 0; ni < 8; ++ni) {
            sc[ni][0] *= 0.125f; sc[ni][1] *= 0.125f;
            sc[ni][2] *= 0.125f; sc[ni][3] *= 0.125f;
        }
        if (kt == qt) {
            int r0 = wid * 16 + gid, r1 = r0 + 8;
            #pragma unroll
            for (int ni = 0; ni < 8; ++ni) {
                int c0 = ni * 8 + tig * 2, c1 = c0 + 1;
                if (c0 > r0) sc[ni][0] = -1e30f;
                if (c1 > r0) sc[ni][1] = -1e30f;
                if (c0 > r1) sc[ni][2] = -1e30f;
                if (c1 > r1) sc[ni][3] = -1e30f;
            }
        }

        // ---- online softmax in registers ----
        float t0 = -1e30f, t1 = -1e30f;
        #pragma unroll
        for (int ni = 0; ni < 8; ++ni) {
            t0 = fmaxf(t0, fmaxf(sc[ni][0], sc[ni][1]));
            t1 = fmaxf(t1, fmaxf(sc[ni][2], sc[ni][3]));
        }
        t0 = fmaxf(t0, __shfl_xor_sync(0xffffffffu, t0, 1));
        t0 = fmaxf(t0, __shfl_xor_sync(0xffffffffu, t0, 2));
        t1 = fmaxf(t1, __shfl_xor_sync(0xffffffffu, t1, 1));
        t1 = fmaxf(t1, __shfl_xor_sync(0xffffffffu, t1, 2));
        float mn0 = fmaxf(m0, t0), mn1 = fmaxf(m1, t1);
        float al0 = __expf(m0 - mn0), al1 = __expf(m1 - mn1);
        m0 = mn0; m1 = mn1;

        float sum0 = 0.0f, sum1 = 0.0f;
        uint32_t pah[4][4], pal[4][4];
        #pragma unroll
        for (int kp = 0; kp < 4; ++kp) {
            float p00 = __expf(sc[2 * kp][0] - mn0);
            float p01 = __expf(sc[2 * kp][1] - mn0);
            float p02 = __expf(sc[2 * kp][2] - mn1);
            float p03 = __expf(sc[2 * kp][3] - mn1);
            float p10 = __expf(sc[2 * kp + 1][0] - mn0);
            float p11 = __expf(sc[2 * kp + 1][1] - mn0);
            float p12 = __expf(sc[2 * kp + 1][2] - mn1);
            float p13 = __expf(sc[2 * kp + 1][3] - mn1);
            sum0 += p00 + p01 + p10 + p11;
            sum1 += p02 + p03 + p12 + p13;
            split2(p00, p01, pah[kp][0], pal[kp][0]);
            split2(p02, p03, pah[kp][1], pal[kp][1]);
            split2(p10, p11, pah[kp][2], pal[kp][2]);
            split2(p12, p13, pah[kp][3], pal[kp][3]);
        }
        sum0 += __shfl_xor_sync(0xffffffffu, sum0, 1);
        sum0 += __shfl_xor_sync(0xffffffffu, sum0, 2);
        sum1 += __shfl_xor_sync(0xffffffffu, sum1, 1);
        sum1 += __shfl_xor_sync(0xffffffffu, sum1, 2);
        l0 = l0 * al0 + sum0;
        l1 = l1 * al1 + sum1;
        #pragma unroll
        for (int ni = 0; ni < 8; ++ni) {
            oacc[ni][0] *= al0; oacc[ni][1] *= al0;
            oacc[ni][2] *= al1; oacc[ni][3] *= al1;
        }

        // ---- O += P V (3-product split, V via trans-ldmatrix) ----
        #pragma unroll
        for (int ks = 0; ks < 4; ++ks) {
            #pragma unroll
            for (int j2 = 0; j2 < 4; ++j2) {
                uint32_t vh0, vh1, vh2, vh3, vl0, vl1, vl2, vl3;
                uint32_t voff = st + 2 * AT_TILE +
                    (uint32_t)((ks * 16 + v_rsel) * AT_PAD + v_csel + j2 * 16) * 2;
                LDM_X4T(vh0, vh1, vh2, vh3, voff);
                LDM_X4T(vl0, vl1, vl2, vl3, voff + AT_TILE);
                MMA16816(oacc[2 * j2],     pah[ks], vh0, vh1);
                MMA16816(oacc[2 * j2],     pal[ks], vh0, vh1);
                MMA16816(oacc[2 * j2],     pah[ks], vl0, vl1);
                MMA16816(oacc[2 * j2 + 1], pah[ks], vh2, vh3);
                MMA16816(oacc[2 * j2 + 1], pal[ks], vh2, vh3);
                MMA16816(oacc[2 * j2 + 1], pah[ks], vl2, vl3);
            }
        }
        __syncthreads();  // all warps done reading stage before overwrite
    }

    // ---- output: ctx bf16 hi/lo ----
    float inv0 = 1.0f / l0, inv1 = 1.0f / l1;
    int grow = qt * 64 + wid * 16 + gid;
    #pragma unroll
    for (int ni = 0; ni < 8; ++ni) {
        size_t i0 = (rowbase + grow) * (size_t)DMODEL + h * HDIM + ni * 8 + tig * 2;
        size_t i1 = i0 + 8 * (size_t)DMODEL;
        uint32_t hh, ll;
        split2(oacc[ni][0] * inv0, oacc[ni][1] * inv0, hh, ll);
        *(uint32_t*)&Oh[i0] = hh;
        *(uint32_t*)&Ol[i0] = ll;
        split2(oacc[ni][2] * inv1, oacc[ni][3] * inv1, hh, ll);
        *(uint32_t*)&Oh[i1] = hh;
        *(uint32_t*)&Ol[i1] = ll;
    }
}

// ---------------- launch -------------------------------------------
static void* sym_addr(const void* sym) {
    void* p = nullptr;
    cudaGetSymbolAddress(&p, sym);
    return p;
}

extern "C" void kernel_launch(void* const* d_in, const int* in_sizes, int n_in,
                              void* d_out, int out_size) {
    const float* x     = (const float*)d_in[0];
    const float* ln1_g = (const float*)d_in[1];
    const float* ln1_b = (const float*)d_in[2];
    const float* Wq    = (const float*)d_in[3];
    const float* Wk    = (const float*)d_in[4];
    const float* Wv    = (const float*)d_in[5];
    const float* Wo    = (const float*)d_in[6];
    const float* ln2_g = (const float*)d_in[7];
    const float* ln2_b = (const float*)d_in[8];
    const float* W1    = (const float*)d_in[9];
    const float* b1    = (const float*)d_in[10];
    const float* W2    = (const float*)d_in[11];
    const float* b2    = (const float*)d_in[12];
    float* out = (float*)d_out;

    float* x2 = (float*)sym_addr(g_x2);
    __nv_bfloat16* lnh  = (__nv_bfloat16*)sym_addr(g_lnh);
    __nv_bfloat16* lnl  = (__nv_bfloat16*)sym_addr(g_lnl);
    __nv_bfloat16* qh   = (__nv_bfloat16*)sym_addr(g_qh);
    __nv_bfloat16* ql   = (__nv_bfloat16*)sym_addr(g_ql);
    __nv_bfloat16* kh   = (__nv_bfloat16*)sym_addr(g_kh);
    __nv_bfloat16* kl   = (__nv_bfloat16*)sym_addr(g_kl);
    __nv_bfloat16* vh   = (__nv_bfloat16*)sym_addr(g_vh);
    __nv_bfloat16* vl   = (__nv_bfloat16*)sym_addr(g_vl);
    __nv_bfloat16* ctxh = (__nv_bfloat16*)sym_addr(g_ctxh);
    __nv_bfloat16* ctxl = (__nv_bfloat16*)sym_addr(g_ctxl);
    __nv_bfloat16* ffh  = (__nv_bfloat16*)sym_addr(g_ffh);
    __nv_bfloat16* ffl  = (__nv_bfloat16*)sym_addr(g_ffl);

    __nv_bfloat16* Bq_h = (__nv_bfloat16*)sym_addr(g_Bq_h);
    __nv_bfloat16* Bq_l = (__nv_bfloat16*)sym_addr(g_Bq_l);
    __nv_bfloat16* Bk_h = (__nv_bfloat16*)sym_addr(g_Bk_h);
    __nv_bfloat16* Bk_l = (__nv_bfloat16*)sym_addr(g_Bk_l);
    __nv_bfloat16* Bv_h = (__nv_bfloat16*)sym_addr(g_Bv_h);
    __nv_bfloat16* Bv_l = (__nv_bfloat16*)sym_addr(g_Bv_l);
    __nv_bfloat16* Bo_h = (__nv_bfloat16*)sym_addr(g_Bo_h);
    __nv_bfloat16* Bo_l = (__nv_bfloat16*)sym_addr(g_Bo_l);
    __nv_bfloat16* B1_h = (__nv_bfloat16*)sym_addr(g_B1_h);
    __nv_bfloat16* B1_l = (__nv_bfloat16*)sym_addr(g_B1_l);
    __nv_bfloat16* B2_h = (__nv_bfloat16*)sym_addr(g_B2_h);
    __nv_bfloat16* B2_l = (__nv_bfloat16*)sym_addr(g_B2_l);

    cudaFuncSetAttribute(hgemm_kernel<0, 0, 0, 1>,
                         cudaFuncAttributeMaxDynamicSharedMemorySize, HG_SMEM_BYTES);
    cudaFuncSetAttribute(hgemm_kernel<0, 0, 1, 0>,
                         cudaFuncAttributeMaxDynamicSharedMemorySize, HG_SMEM_BYTES);
    cudaFuncSetAttribute(hgemm_kernel<1, 1, 0, 1>,
                         cudaFuncAttributeMaxDynamicSharedMemorySize, HG_SMEM_BYTES);
    cudaFuncSetAttribute(hgemm_kernel<0, 1, 1, 0>,
                         cudaFuncAttributeMaxDynamicSharedMemorySize, HG_SMEM_BYTES);
    cudaFuncSetAttribute(attn_kernel,
                         cudaFuncAttributeMaxDynamicSharedMemorySize, AT_SMEM);

    dim3 blk128(128), blk256(256);
    dim3 g1k(DMODEL / 64, MROWS / 128);        // (16, 32)
    dim3 g2k(2 * DMODEL / 64, MROWS / 128);    // (32, 32)

    // 0: weight prep
    wsplit_all_kernel<<<8192, blk256>>>(Wq, Bq_h, Bq_l, Wk, Bk_h, Bk_l,
                                        Wv, Bv_h, Bv_l, Wo, Bo_h, Bo_l,
                                        W1, B1_h, B1_l, W2, B2_h, B2_l);
    // 1: LN1
    ln_kernel<<<MROWS, blk256>>>(x, ln1_g, ln1_b, lnh, lnl);
    // 2-4: QKV projections -> bf16 hi/lo
    hgemm_kernel<0, 0, 0, 1><<<g1k, blk128, HG_SMEM_BYTES>>>(
        lnh, lnl, Bq_h, Bq_l, nullptr, nullptr, nullptr, qh, ql,
        MROWS, DMODEL, DMODEL);
    hgemm_kernel<0, 0, 0, 1><<<g1k, blk128, HG_SMEM_BYTES>>>(
        lnh, lnl, Bk_h, Bk_l, nullptr, nullptr, nullptr, kh, kl,
        MROWS, DMODEL, DMODEL);
    hgemm_kernel<0, 0, 0, 1><<<g1k, blk128, HG_SMEM_BYTES>>>(
        lnh, lnl, Bv_h, Bv_l, nullptr, nullptr, nullptr, vh, vl,
        MROWS, DMODEL, DMODEL);
    // 5: tensor-core attention -> ctx bf16 hi/lo
    attn_kernel<<<dim3(32, 32), blk128, AT_SMEM>>>(qh, ql, kh, kl, vh, vl,
                                                   ctxh, ctxl);
    // 6: output projection + residual(x) -> x2 fp32
    hgemm_kernel<0, 0, 1, 0><<<g1k, blk128, HG_SMEM_BYTES>>>(
        ctxh, ctxl, Bo_h, Bo_l, nullptr, x, x2, nullptr, nullptr,
        MROWS, DMODEL, DMODEL);
    // 7: LN2
    ln_kernel<<<MROWS, blk256>>>(x2, ln2_g, ln2_b, lnh, lnl);
    // 8: FFN up + bias + GELU -> ff bf16 hi/lo
    hgemm_kernel<1, 1, 0, 1><<<g2k, blk128, HG_SMEM_BYTES>>>(
        lnh, lnl, B1_h, B1_l, b1, nullptr, nullptr, ffh, ffl,
        MROWS, 2 * DMODEL, DMODEL);
    // 9: FFN down + bias + residual(x2) -> out fp32
    hgemm_kernel<0, 1, 1, 0><<<g1k, blk128, HG_SMEM_BYTES>>>(
        ffh, ffl, B2_h, B2_l, b2, x2, out, nullptr, nullptr,
        MROWS, DMODEL, 2 * DMODEL);
}

// round 9
// speedup vs baseline: 2.8524x; 1.0715x over previous
#include <cuda_runtime.h>
#include <cuda_bf16.h>
#include <math.h>
#include <stdint.h>

#define DMODEL 1024
#define SEQT   2048
#define BATCH  2
#define MROWS  4096   // BATCH * SEQT
#define NHEAD  16
#define HDIM   64
#define DM3    (3 * DMODEL)

// ---------------- scratch (static device allocations) ----------------
__device__ float g_x2 [MROWS * DMODEL];
// bf16 hi/lo split activations
__device__ __nv_bfloat16 g_lnh [MROWS * DMODEL], g_lnl [MROWS * DMODEL];
__device__ __nv_bfloat16 g_qkvh[MROWS * DM3],    g_qkvl[MROWS * DM3];
__device__ __nv_bfloat16 g_ctxh[MROWS * DMODEL], g_ctxl[MROWS * DMODEL];
__device__ __nv_bfloat16 g_ffh [MROWS * 2 * DMODEL], g_ffl [MROWS * 2 * DMODEL];

// transposed + split weights: [N][K] bf16 hi/lo
__device__ __nv_bfloat16 g_Bqkv_h[DM3 * DMODEL], g_Bqkv_l[DM3 * DMODEL];
__device__ __nv_bfloat16 g_Bo_h[DMODEL * DMODEL], g_Bo_l[DMODEL * DMODEL];
__device__ __nv_bfloat16 g_B1_h[2 * DMODEL * DMODEL], g_B1_l[2 * DMODEL * DMODEL];
__device__ __nv_bfloat16 g_B2_h[2 * DMODEL * DMODEL], g_B2_l[2 * DMODEL * DMODEL];

// ---------------- helpers --------------------------------------------
__device__ __forceinline__ uint32_t smem_u32(const void* p) {
    uint32_t a;
    asm("{ .reg .u64 t; cvta.to.shared.u64 t, %1; cvt.u32.u64 %0, t; }"
        : "=r"(a) : "l"(p));
    return a;
}
__device__ __forceinline__ float gelu_exact(float x) {
    return 0.5f * x * (1.0f + erff(x * 0.70710678118654752f));
}
__device__ __forceinline__ void split2(float x, float y, uint32_t& h, uint32_t& l) {
    __nv_bfloat162 hh = __float22bfloat162_rn(make_float2(x, y));
    float2 f = __bfloat1622float2(hh);
    __nv_bfloat162 ll = __float22bfloat162_rn(make_float2(x - f.x, y - f.y));
    h = *(uint32_t*)&hh;
    l = *(uint32_t*)&ll;
}

#define LDM_X4(r0, r1, r2, r3, addr) \
    asm volatile("ldmatrix.sync.aligned.m8n8.x4.shared.b16 {%0,%1,%2,%3}, [%4];" \
        : "=r"(r0), "=r"(r1), "=r"(r2), "=r"(r3) : "r"(addr))
#define LDM_X4T(r0, r1, r2, r3, addr) \
    asm volatile("ldmatrix.sync.aligned.m8n8.x4.trans.shared.b16 {%0,%1,%2,%3}, [%4];" \
        : "=r"(r0), "=r"(r1), "=r"(r2), "=r"(r3) : "r"(addr))

#define MMA16816(d, a, b0, b1) \
    asm volatile("mma.sync.aligned.m16n8k16.row.col.f32.bf16.bf16.f32 " \
        "{%0,%1,%2,%3}, {%4,%5,%6,%7}, {%8,%9}, {%0,%1,%2,%3};" \
        : "+f"((d)[0]), "+f"((d)[1]), "+f"((d)[2]), "+f"((d)[3]) \
        : "r"((a)[0]), "r"((a)[1]), "r"((a)[2]), "r"((a)[3]), \
          "r"(b0), "r"(b1))

#define CP16(dst, src) \
    asm volatile("cp.async.cg.shared.global [%0], [%1], 16;" \
        :: "r"(dst), "l"(src))
#define CP_COMMIT() asm volatile("cp.async.commit_group;")
#define CP_WAIT1()  asm volatile("cp.async.wait_group 1;")
#define CP_WAIT0()  asm volatile("cp.async.wait_group 0;")

// ---------------- weight prep: all 6 weights in ONE launch -----------
// Q/K/V write into concatenated g_Bqkv (rows w*1024 + n).
__global__ void __launch_bounds__(256) wsplit_all_kernel(
    const float* __restrict__ Wq, const float* __restrict__ Wk,
    const float* __restrict__ Wv,
    __nv_bfloat16* __restrict__ Bqkv_h, __nv_bfloat16* __restrict__ Bqkv_l,
    const float* __restrict__ Wo, __nv_bfloat16* __restrict__ Bo_h, __nv_bfloat16* __restrict__ Bo_l,
    const float* __restrict__ W1, __nv_bfloat16* __restrict__ B1_h, __nv_bfloat16* __restrict__ B1_l,
    const float* __restrict__ W2, __nv_bfloat16* __restrict__ B2_h, __nv_bfloat16* __restrict__ B2_l) {
    __shared__ float t[32][33];
    int bid = blockIdx.x;
    const float* W;
    __nv_bfloat16 *Th, *Tl;
    int K, N, k0, n0, nout;
    if (bid < 4096) {
        int w = bid >> 10, lb = bid & 1023;
        K = DMODEL; N = DMODEL;
        k0 = (lb & 31) * 32; n0 = (lb >> 5) * 32;
        if (w < 3) {
            W = (w == 0) ? Wq : (w == 1) ? Wk : Wv;
            Th = Bqkv_h; Tl = Bqkv_l;
            nout = n0 + w * DMODEL;
        } else {
            W = Wo; Th = Bo_h; Tl = Bo_l; nout = n0;
        }
    } else if (bid < 6144) {
        int lb = bid - 4096;
        K = DMODEL; N = 2 * DMODEL;
        k0 = (lb & 31) * 32; n0 = (lb >> 5) * 32;
        W = W1; Th = B1_h; Tl = B1_l; nout = n0;
    } else {
        int lb = bid - 6144;
        K = 2 * DMODEL; N = DMODEL;
        k0 = (lb & 63) * 32; n0 = (lb >> 6) * 32;
        W = W2; Th = B2_h; Tl = B2_l; nout = n0;
    }
    int tx = threadIdx.x & 31, ty = threadIdx.x >> 5;
    #pragma unroll
    for (int i = 0; i < 4; ++i)
        t[ty + i * 8][tx] = W[(size_t)(k0 + ty + i * 8) * N + n0 + tx];
    __syncthreads();
    #pragma unroll
    for (int i = 0; i < 4; ++i) {
        int n = nout + ty + i * 8, k = k0 + tx;
        float x = t[tx][ty + i * 8];
        __nv_bfloat16 h = __float2bfloat16_rn(x);
        float lo = x - __bfloat162float(h);
        Th[(size_t)n * K + k] = h;
        Tl[(size_t)n * K + k] = __float2bfloat16_rn(lo);
    }
}

// ---------------- LayerNorm -> bf16 hi/lo ----------------------------
__global__ void __launch_bounds__(256) ln_kernel(const float* __restrict__ x,
                                                 const float* __restrict__ g,
                                                 const float* __restrict__ b,
                                                 __nv_bfloat16* __restrict__ outh,
                                                 __nv_bfloat16* __restrict__ outl) {
    int row = blockIdx.x;
    int tid = threadIdx.x;
    const float4* xr = (const float4*)(x + (size_t)row * DMODEL);
    float4 v = xr[tid];
    float s  = v.x + v.y + v.z + v.w;
    float ss = v.x * v.x + v.y * v.y + v.z * v.z + v.w * v.w;
    #pragma unroll
    for (int o = 16; o > 0; o >>= 1) {
        s  += __shfl_xor_sync(0xffffffffu, s,  o);
        ss += __shfl_xor_sync(0xffffffffu, ss, o);
    }
    __shared__ float sh[16];
    int w = tid >> 5;
    if ((tid & 31) == 0) { sh[w] = s; sh[8 + w] = ss; }
    __syncthreads();
    if (tid < 32) {
        float a  = (tid < 8) ? sh[tid]     : 0.0f;
        float a2 = (tid < 8) ? sh[8 + tid] : 0.0f;
        #pragma unroll
        for (int o = 4; o > 0; o >>= 1) {
            a  += __shfl_xor_sync(0xffffffffu, a,  o);
            a2 += __shfl_xor_sync(0xffffffffu, a2, o);
        }
        if (tid == 0) { sh[0] = a; sh[1] = a2; }
    }
    __syncthreads();
    float mean = sh[0] * (1.0f / DMODEL);
    float var  = sh[1] * (1.0f / DMODEL) - mean * mean;
    float rstd = rsqrtf(var + 1e-5f);
    float4 gg = ((const float4*)g)[tid];
    float4 bb = ((const float4*)b)[tid];
    float o0 = (v.x - mean) * rstd * gg.x + bb.x;
    float o1 = (v.y - mean) * rstd * gg.y + bb.y;
    float o2 = (v.z - mean) * rstd * gg.z + bb.z;
    float o3 = (v.w - mean) * rstd * gg.w + bb.w;
    uint2 h, l;
    split2(o0, o1, h.x, l.x);
    split2(o2, o3, h.y, l.y);
    ((uint2*)(outh + (size_t)row * DMODEL))[tid] = h;
    ((uint2*)(outl + (size_t)row * DMODEL))[tid] = l;
}

// ---------------- HMMA GEMM: 256 thr, tile 128x128, 2 stages ---------
// 8 warps as 2m x 4n; warp tile 64x32 (inner loop identical to proven).
// PAD 40 elems (80B rows). stage = A 2*10240 + B 2*10240 = 40960B.
// 2 stages = 81920B -> 2 CTAs/SM (launch_bounds caps regs at 128).
#define HPAD 40
#define HG_A_L   10240
#define HG_B     20480
#define HG_B_L   10240
#define HG_STAGE 40960
#define HG_SMEM_BYTES (2 * HG_STAGE)

template <int GELU, int HAS_BIAS, int HAS_RES, int OSPLIT>
__global__ void __launch_bounds__(256, 2) hgemm_kernel(
    const __nv_bfloat16* __restrict__ Ah, const __nv_bfloat16* __restrict__ Al,
    const __nv_bfloat16* __restrict__ Bh, const __nv_bfloat16* __restrict__ Bl,
    const float* __restrict__ bias, const float* __restrict__ res,
    float* __restrict__ C, __nv_bfloat16* __restrict__ Ch,
    __nv_bfloat16* __restrict__ Cl, int M, int N, int K) {
    extern __shared__ __align__(16) char smem[];
    uint32_t uS = smem_u32(smem);

    int tid = threadIdx.x;
    int lane = tid & 31, wid = tid >> 5;
    int wm = wid >> 2, wn = wid & 3;
    int bm = blockIdx.y * 128, bn = blockIdx.x * 128;

    float acc[4][4][4];
    #pragma unroll
    for (int i = 0; i < 4; ++i)
        #pragma unroll
        for (int j = 0; j < 4; ++j)
            #pragma unroll
            for (int k = 0; k < 4; ++k) acc[i][j][k] = 0.0f;

    int q = lane >> 3, rr = lane & 7;
    int a_row = wm * 64 + (q & 1) * 8 + rr;
    int a_col = (q >> 1) * 8;
    int b_row = wn * 32 + (q >> 1) * 8 + rr;
    int b_col = (q & 1) * 8;

    int ar = tid >> 2, ac8 = (tid & 3) << 3;   // rows 0..63, cols 0..31
    const int NC = K >> 5;

    auto load_chunk = [&](int c, int s) {
        uint32_t sb = uS + (uint32_t)s * HG_STAGE;
        int kc = c << 5;
        #pragma unroll
        for (int i = 0; i < 2; ++i) {
            int r = ar + i * 64;
            uint32_t d = sb + (uint32_t)(r * HPAD + ac8) * 2;
            CP16(d, Ah + (size_t)(bm + r) * K + kc + ac8);
            CP16(d + HG_A_L, Al + (size_t)(bm + r) * K + kc + ac8);
        }
        #pragma unroll
        for (int i = 0; i < 2; ++i) {
            int r = ar + i * 64;
            uint32_t d = sb + HG_B + (uint32_t)(r * HPAD + ac8) * 2;
            CP16(d, Bh + (size_t)(bn + r) * K + kc + ac8);
            CP16(d + HG_B_L, Bl + (size_t)(bn + r) * K + kc + ac8);
        }
        CP_COMMIT();
    };

    load_chunk(0, 0);

    for (int c = 0; c < NC; ++c) {
        if (c + 1 < NC) { load_chunk(c + 1, (c + 1) & 1); CP_WAIT1(); }
        else            { CP_WAIT0(); }
        __syncthreads();

        uint32_t sb = uS + (uint32_t)(c & 1) * HG_STAGE;
        #pragma unroll
        for (int ks = 0; ks < 2; ++ks) {
            uint32_t ahf[4][4], alf[4][4];
            #pragma unroll
            for (int mi = 0; mi < 4; ++mi) {
                uint32_t off = sb + (uint32_t)((a_row + mi * 16) * HPAD + a_col + ks * 16) * 2;
                LDM_X4(ahf[mi][0], ahf[mi][1], ahf[mi][2], ahf[mi][3], off);
                LDM_X4(alf[mi][0], alf[mi][1], alf[mi][2], alf[mi][3], off + HG_A_L);
            }
            #pragma unroll
            for (int j2 = 0; j2 < 2; ++j2) {
                uint32_t bhf[2][2], blf[2][2];
                uint32_t off = sb + HG_B +
                    (uint32_t)((b_row + j2 * 16) * HPAD + b_col + ks * 16) * 2;
                LDM_X4(bhf[0][0], bhf[0][1], bhf[1][0], bhf[1][1], off);
                LDM_X4(blf[0][0], blf[0][1], blf[1][0], blf[1][1], off + HG_B_L);
                #pragma unroll
                for (int mi = 0; mi < 4; ++mi)
                    #pragma unroll
                    for (int nj = 0; nj < 2; ++nj) {
                        int ni = j2 * 2 + nj;
                        MMA16816(acc[mi][ni], ahf[mi], bhf[nj][0], bhf[nj][1]);
                        MMA16816(acc[mi][ni], alf[mi], bhf[nj][0], bhf[nj][1]);
                        MMA16816(acc[mi][ni], ahf[mi], blf[nj][0], blf[nj][1]);
                    }
            }
        }
        __syncthreads();
    }

    // epilogue
    int gid = lane >> 2, tig = lane & 3;
    #pragma unroll
    for (int mi = 0; mi < 4; ++mi) {
        #pragma unroll
        for (int ni = 0; ni < 4; ++ni) {
            int row0 = bm + wm * 64 + mi * 16 + gid;
            int col  = bn + wn * 32 + ni * 8 + tig * 2;
            float c0 = acc[mi][ni][0], c1 = acc[mi][ni][1];
            float c2 = acc[mi][ni][2], c3 = acc[mi][ni][3];
            if (HAS_BIAS) {
                float b0 = bias[col], b1v = bias[col + 1];
                c0 += b0; c1 += b1v; c2 += b0; c3 += b1v;
            }
            if (GELU) {
                c0 = gelu_exact(c0); c1 = gelu_exact(c1);
                c2 = gelu_exact(c2); c3 = gelu_exact(c3);
            }
            if (HAS_RES) {
                float2 r0 = *(const float2*)&res[(size_t)row0 * N + col];
                float2 r1 = *(const float2*)&res[(size_t)(row0 + 8) * N + col];
                c0 += r0.x; c1 += r0.y; c2 += r1.x; c3 += r1.y;
            }
            if (OSPLIT) {
                uint32_t h0, l0, h1, l1;
                split2(c0, c1, h0, l0);
                split2(c2, c3, h1, l1);
                *(uint32_t*)&Ch[(size_t)row0 * N + col] = h0;
                *(uint32_t*)&Cl[(size_t)row0 * N + col] = l0;
                *(uint32_t*)&Ch[(size_t)(row0 + 8) * N + col] = h1;
                *(uint32_t*)&Cl[(size_t)(row0 + 8) * N + col] = l1;
            } else {
                float2 o0; o0.x = c0; o0.y = c1;
                float2 o1; o1.x = c2; o1.y = c3;
                *(float2*)&C[(size_t)row0 * N + col] = o0;
                *(float2*)&C[(size_t)(row0 + 8) * N + col] = o1;
            }
        }
    }
}

// ---------------- Tensor-core flash attention -------------------------
// Q/K/V come from the merged [M][3072] hi/lo arrays (col base 0/1024/2048).
#define AT_PAD   72
#define AT_QL    9216
#define AT_KV    18432
#define AT_TILE  9216
#define AT_STAGE 36864
#define AT_SMEM  (AT_KV + 2 * AT_STAGE)  // 92160

__global__ void __launch_bounds__(128) attn_kernel(
    const __nv_bfloat16* __restrict__ QKVh, const __nv_bfloat16* __restrict__ QKVl,
    __nv_bfloat16* __restrict__ Oh, __nv_bfloat16* __restrict__ Ol) {
    extern __shared__ __align__(16) char smem[];
    uint32_t uS = smem_u32(smem);

    int qt = 31 - (int)blockIdx.x;
    int bh = blockIdx.y;
    int b = bh >> 4, h = bh & 15;
    int tid = threadIdx.x, lane = tid & 31, wid = tid >> 5;
    int gid = lane >> 2, tig = lane & 3;
    int q = lane >> 3, rr = lane & 7;

    size_t rowbase = (size_t)b * SEQT;

    auto ld_tile = [&](const __nv_bfloat16* G, uint32_t dst, int trow, int cbase) {
        #pragma unroll
        for (int i = 0; i < 4; ++i) {
            int idx = tid + i * 128;
            int r = idx >> 3, c8 = (idx & 7) << 3;
            CP16(dst + (uint32_t)(r * AT_PAD + c8) * 2,
                 G + (rowbase + trow + r) * (size_t)DM3 + cbase + h * HDIM + c8);
        }
    };

    // prologue: Q tile + KV tile 0
    ld_tile(QKVh, uS, qt * 64, 0);
    ld_tile(QKVl, uS + AT_QL, qt * 64, 0);
    ld_tile(QKVh, uS + AT_KV, 0, DMODEL);
    ld_tile(QKVl, uS + AT_KV + AT_TILE, 0, DMODEL);
    ld_tile(QKVh, uS + AT_KV + 2 * AT_TILE, 0, 2 * DMODEL);
    ld_tile(QKVl, uS + AT_KV + 3 * AT_TILE, 0, 2 * DMODEL);
    CP_COMMIT();

    float oacc[8][4];
    #pragma unroll
    for (int i = 0; i < 8; ++i)
        #pragma unroll
        for (int j = 0; j < 4; ++j) oacc[i][j] = 0.0f;
    float m0 = -1e30f, m1 = -1e30f, l0 = 0.0f, l1 = 0.0f;

    int a_row   = wid * 16 + (q & 1) * 8 + rr;
    int a_csel  = (q >> 1) * 8;
    int b_rsel  = (q >> 1) * 8 + rr;
    int b_csel  = (q & 1) * 8;
    int v_rsel  = (q & 1) * 8 + rr;
    int v_csel  = (q >> 1) * 8;

    for (int kt = 0; kt <= qt; ++kt) {
        uint32_t st = uS + AT_KV + (uint32_t)(kt & 1) * AT_STAGE;
        if (kt < qt) {
            uint32_t s2 = uS + AT_KV + (uint32_t)((kt + 1) & 1) * AT_STAGE;
            ld_tile(QKVh, s2, (kt + 1) * 64, DMODEL);
            ld_tile(QKVl, s2 + AT_TILE, (kt + 1) * 64, DMODEL);
            ld_tile(QKVh, s2 + 2 * AT_TILE, (kt + 1) * 64, 2 * DMODEL);
            ld_tile(QKVl, s2 + 3 * AT_TILE, (kt + 1) * 64, 2 * DMODEL);
            CP_COMMIT();
            CP_WAIT1();
        } else {
            CP_WAIT0();
        }
        __syncthreads();

        // ---- S = Q K^T (3-product split) ----
        float sc[8][4];
        #pragma unroll
        for (int i = 0; i < 8; ++i)
            #pragma unroll
            for (int j = 0; j < 4; ++j) sc[i][j] = 0.0f;

        #pragma unroll
        for (int ks = 0; ks < 4; ++ks) {
            uint32_t qhf[4], qlf[4];
            uint32_t aoff = (uint32_t)(a_row * AT_PAD + a_csel + ks * 16) * 2;
            LDM_X4(qhf[0], qhf[1], qhf[2], qhf[3], uS + aoff);
            LDM_X4(qlf[0], qlf[1], qlf[2], qlf[3], uS + AT_QL + aoff);
            #pragma unroll
            for (int j2 = 0; j2 < 4; ++j2) {
                uint32_t kh0, kh1, kh2, kh3, kl0, kl1, kl2, kl3;
                uint32_t boff = st +
                    (uint32_t)((j2 * 16 + b_rsel) * AT_PAD + b_csel + ks * 16) * 2;
                LDM_X4(kh0, kh1, kh2, kh3, boff);
                LDM_X4(kl0, kl1, kl2, kl3, boff + AT_TILE);
                MMA16816(sc[2 * j2],     qhf, kh0, kh1);
                MMA16816(sc[2 * j2],     qlf, kh0, kh1);
                MMA16816(sc[2 * j2],     qhf, kl0, kl1);
                MMA16816(sc[2 * j2 + 1], qhf, kh2, kh3);
                MMA16816(sc[2 * j2 + 1], qlf, kh2, kh3);
                MMA16816(sc[2 * j2 + 1], qhf, kl2, kl3);
            }
        }

        // scale + causal mask
        #pragma unroll
        for (int ni = 0; ni < 8; ++ni) {
            sc[ni][0] *= 0.125f; sc[ni][1] *= 0.125f;
            sc[ni][2] *= 0.125f; sc[ni][3] *= 0.125f;
        }
        if (kt == qt) {
            int r0 = wid * 16 + gid, r1 = r0 + 8;
            #pragma unroll
            for (int ni = 0; ni < 8; ++ni) {
                int c0 = ni * 8 + tig * 2, c1 = c0 + 1;
                if (c0 > r0) sc[ni][0] = -1e30f;
                if (c1 > r0) sc[ni][1] = -1e30f;
                if (c0 > r1) sc[ni][2] = -1e30f;
                if (c1 > r1) sc[ni][3] = -1e30f;
            }
        }

        // ---- online softmax in registers ----
        float t0 = -1e30f, t1 = -1e30f;
        #pragma unroll
        for (int ni = 0; ni < 8; ++ni) {
            t0 = fmaxf(t0, fmaxf(sc[ni][0], sc[ni][1]));
            t1 = fmaxf(t1, fmaxf(sc[ni][2], sc[ni][3]));
        }
        t0 = fmaxf(t0, __shfl_xor_sync(0xffffffffu, t0, 1));
        t0 = fmaxf(t0, __shfl_xor_sync(0xffffffffu, t0, 2));
        t1 = fmaxf(t1, __shfl_xor_sync(0xffffffffu, t1, 1));
        t1 = fmaxf(t1, __shfl_xor_sync(0xffffffffu, t1, 2));
        float mn0 = fmaxf(m0, t0), mn1 = fmaxf(m1, t1);
        float al0 = __expf(m0 - mn0), al1 = __expf(m1 - mn1);
        m0 = mn0; m1 = mn1;

        float sum0 = 0.0f, sum1 = 0.0f;
        uint32_t pah[4][4], pal[4][4];
        #pragma unroll
        for (int kp = 0; kp < 4; ++kp) {
            float p00 = __expf(sc[2 * kp][0] - mn0);
            float p01 = __expf(sc[2 * kp][1] - mn0);
            float p02 = __expf(sc[2 * kp][2] - mn1);
            float p03 = __expf(sc[2 * kp][3] - mn1);
            float p10 = __expf(sc[2 * kp + 1][0] - mn0);
            float p11 = __expf(sc[2 * kp + 1][1] - mn0);
            float p12 = __expf(sc[2 * kp + 1][2] - mn1);
            float p13 = __expf(sc[2 * kp + 1][3] - mn1);
            sum0 += p00 + p01 + p10 + p11;
            sum1 += p02 + p03 + p12 + p13;
            split2(p00, p01, pah[kp][0], pal[kp][0]);
            split2(p02, p03, pah[kp][1], pal[kp][1]);
            split2(p10, p11, pah[kp][2], pal[kp][2]);
            split2(p12, p13, pah[kp][3], pal[kp][3]);
        }
        sum0 += __shfl_xor_sync(0xffffffffu, sum0, 1);
        sum0 += __shfl_xor_sync(0xffffffffu, sum0, 2);
        sum1 += __shfl_xor_sync(0xffffffffu, sum1, 1);
        sum1 += __shfl_xor_sync(0xffffffffu, sum1, 2);
        l0 = l0 * al0 + sum0;
        l1 = l1 * al1 + sum1;
        #pragma unroll
        for (int ni = 0; ni < 8; ++ni) {
            oacc[ni][0] *= al0; oacc[ni][1] *= al0;
            oacc[ni][2] *= al1; oacc[ni][3] *= al1;
        }

        // ---- O += P V (3-product split, V via trans-ldmatrix) ----
        #pragma unroll
        for (int ks = 0; ks < 4; ++ks) {
            #pragma unroll
            for (int j2 = 0; j2 < 4; ++j2) {
                uint32_t vh0, vh1, vh2, vh3, vl0, vl1, vl2, vl3;
                uint32_t voff = st + 2 * AT_TILE +
                    (uint32_t)((ks * 16 + v_rsel) * AT_PAD + v_csel + j2 * 16) * 2;
                LDM_X4T(vh0, vh1, vh2, vh3, voff);
                LDM_X4T(vl0, vl1, vl2, vl3, voff + AT_TILE);
                MMA16816(oacc[2 * j2],     pah[ks], vh0, vh1);
                MMA16816(oacc[2 * j2],     pal[ks], vh0, vh1);
                MMA16816(oacc[2 * j2],     pah[ks], vl0, vl1);
                MMA16816(oacc[2 * j2 + 1], pah[ks], vh2, vh3);
                MMA16816(oacc[2 * j2 + 1], pal[ks], vh2, vh3);
                MMA16816(oacc[2 * j2 + 1], pah[ks], vl2, vl3);
            }
        }
        __syncthreads();
    }

    // ---- output: ctx bf16 hi/lo ([M][1024] layout) ----
    float inv0 = 1.0f / l0, inv1 = 1.0f / l1;
    int grow = qt * 64 + wid * 16 + gid;
    #pragma unroll
    for (int ni = 0; ni < 8; ++ni) {
        size_t i0 = (rowbase + grow) * (size_t)DMODEL + h * HDIM + ni * 8 + tig * 2;
        size_t i1 = i0 + 8 * (size_t)DMODEL;
        uint32_t hh, ll;
        split2(oacc[ni][0] * inv0, oacc[ni][1] * inv0, hh, ll);
        *(uint32_t*)&Oh[i0] = hh;
        *(uint32_t*)&Ol[i0] = ll;
        split2(oacc[ni][2] * inv1, oacc[ni][3] * inv1, hh, ll);
        *(uint32_t*)&Oh[i1] = hh;
        *(uint32_t*)&Ol[i1] = ll;
    }
}

// ---------------- launch -------------------------------------------
static void* sym_addr(const void* sym) {
    void* p = nullptr;
    cudaGetSymbolAddress(&p, sym);
    return p;
}

extern "C" void kernel_launch(void* const* d_in, const int* in_sizes, int n_in,
                              void* d_out, int out_size) {
    const float* x     = (const float*)d_in[0];
    const float* ln1_g = (const float*)d_in[1];
    const float* ln1_b = (const float*)d_in[2];
    const float* Wq    = (const float*)d_in[3];
    const float* Wk    = (const float*)d_in[4];
    const float* Wv    = (const float*)d_in[5];
    const float* Wo    = (const float*)d_in[6];
    const float* ln2_g = (const float*)d_in[7];
    const float* ln2_b = (const float*)d_in[8];
    const float* W1    = (const float*)d_in[9];
    const float* b1    = (const float*)d_in[10];
    const float* W2    = (const float*)d_in[11];
    const float* b2    = (const float*)d_in[12];
    float* out = (float*)d_out;

    float* x2 = (float*)sym_addr(g_x2);
    __nv_bfloat16* lnh   = (__nv_bfloat16*)sym_addr(g_lnh);
    __nv_bfloat16* lnl   = (__nv_bfloat16*)sym_addr(g_lnl);
    __nv_bfloat16* qkvh  = (__nv_bfloat16*)sym_addr(g_qkvh);
    __nv_bfloat16* qkvl  = (__nv_bfloat16*)sym_addr(g_qkvl);
    __nv_bfloat16* ctxh  = (__nv_bfloat16*)sym_addr(g_ctxh);
    __nv_bfloat16* ctxl  = (__nv_bfloat16*)sym_addr(g_ctxl);
    __nv_bfloat16* ffh   = (__nv_bfloat16*)sym_addr(g_ffh);
    __nv_bfloat16* ffl   = (__nv_bfloat16*)sym_addr(g_ffl);

    __nv_bfloat16* Bqkv_h = (__nv_bfloat16*)sym_addr(g_Bqkv_h);
    __nv_bfloat16* Bqkv_l = (__nv_bfloat16*)sym_addr(g_Bqkv_l);
    __nv_bfloat16* Bo_h = (__nv_bfloat16*)sym_addr(g_Bo_h);
    __nv_bfloat16* Bo_l = (__nv_bfloat16*)sym_addr(g_Bo_l);
    __nv_bfloat16* B1_h = (__nv_bfloat16*)sym_addr(g_B1_h);
    __nv_bfloat16* B1_l = (__nv_bfloat16*)sym_addr(g_B1_l);
    __nv_bfloat16* B2_h = (__nv_bfloat16*)sym_addr(g_B2_h);
    __nv_bfloat16* B2_l = (__nv_bfloat16*)sym_addr(g_B2_l);

    cudaFuncSetAttribute(hgemm_kernel<0, 0, 0, 1>,
                         cudaFuncAttributeMaxDynamicSharedMemorySize, HG_SMEM_BYTES);
    cudaFuncSetAttribute(hgemm_kernel<0, 0, 1, 0>,
                         cudaFuncAttributeMaxDynamicSharedMemorySize, HG_SMEM_BYTES);
    cudaFuncSetAttribute(hgemm_kernel<1, 1, 0, 1>,
                         cudaFuncAttributeMaxDynamicSharedMemorySize, HG_SMEM_BYTES);
    cudaFuncSetAttribute(hgemm_kernel<0, 1, 1, 0>,
                         cudaFuncAttributeMaxDynamicSharedMemorySize, HG_SMEM_BYTES);
    cudaFuncSetAttribute(attn_kernel,
                         cudaFuncAttributeMaxDynamicSharedMemorySize, AT_SMEM);

    dim3 blk128(128), blk256(256);
    dim3 gqkv(DM3 / 128, MROWS / 128);         // (24, 32)
    dim3 g1k(DMODEL / 128, MROWS / 128);       // (8, 32)
    dim3 g2k(2 * DMODEL / 128, MROWS / 128);   // (16, 32)

    // 0: weight prep (QKV concatenated)
    wsplit_all_kernel<<<8192, blk256>>>(Wq, Wk, Wv, Bqkv_h, Bqkv_l,
                                        Wo, Bo_h, Bo_l,
                                        W1, B1_h, B1_l, W2, B2_h, B2_l);
    // 1: LN1
    ln_kernel<<<MROWS, blk256>>>(x, ln1_g, ln1_b, lnh, lnl);
    // 2: merged QKV projection -> [M][3072] bf16 hi/lo
    hgemm_kernel<0, 0, 0, 1><<<gqkv, blk256, HG_SMEM_BYTES>>>(
        lnh, lnl, Bqkv_h, Bqkv_l, nullptr, nullptr, nullptr, qkvh, qkvl,
        MROWS, DM3, DMODEL);
    // 3: tensor-core attention -> ctx bf16 hi/lo
    attn_kernel<<<dim3(32, 32), blk128, AT_SMEM>>>(qkvh, qkvl, ctxh, ctxl);
    // 4: output projection + residual(x) -> x2 fp32
    hgemm_kernel<0, 0, 1, 0><<<g1k, blk256, HG_SMEM_BYTES>>>(
        ctxh, ctxl, Bo_h, Bo_l, nullptr, x, x2, nullptr, nullptr,
        MROWS, DMODEL, DMODEL);
    // 5: LN2
    ln_kernel<<<MROWS, blk256>>>(x2, ln2_g, ln2_b, lnh, lnl);
    // 6: FFN up + bias + GELU -> ff bf16 hi/lo
    hgemm_kernel<1, 1, 0, 1><<<g2k, blk256, HG_SMEM_BYTES>>>(
        lnh, lnl, B1_h, B1_l, b1, nullptr, nullptr, ffh, ffl,
        MROWS, 2 * DMODEL, DMODEL);
    // 7: FFN down + bias + residual(x2) -> out fp32
    hgemm_kernel<0, 1, 1, 0><<<g1k, blk256, HG_SMEM_BYTES>>>(
        ffh, ffl, B2_h, B2_l, b2, x2, out, nullptr, nullptr,
        MROWS, DMODEL, 2 * DMODEL);
}